// round 15
// baseline (speedup 1.0000x reference)
#include <cuda_runtime.h>
#include <cuda_fp16.h>
#include <math.h>
#include <stdint.h>

#define N_NODES  50000
#define N_EDGES  800000
#define N_GRAPHS 256
#define DMAX     512
#define GRUH     256
#define NPART    196   // ceil(50000/256)

// weight segments (halves): L0 64x128, L1 128x256, L2 256x512
#define WOFF0 0
#define WOFF1 8192
#define WOFF2 40960
#define WTOT  172032

// ---------------- scratch (device globals; no allocation allowed) ----------------
__device__ __align__(16) __half g_hbuf[(size_t)N_NODES * DMAX];   // layer outputs / xh (fp16)
__device__ __align__(16) __half g_abuf[(size_t)N_NODES * 256];    // agg outputs / GEMM A (fp16)
__device__ __align__(16) __half g_bwh[WTOT];                      // weights fp16, [n][k]
__device__ float g_dinv[N_NODES];
__device__ int   g_counts[N_NODES];
__device__ int   g_rank[N_EDGES];
__device__ int   g_offs[N_NODES + 1];
__device__ int   g_csrc[N_EDGES];
__device__ int   g_gcounts[N_GRAPHS];
__device__ int   g_goffs[N_GRAPHS + 1];
__device__ float g_gate[N_NODES];
__device__ __align__(16) float g_emb[N_GRAPHS * 512];
__device__ float g_h1[N_GRAPHS * GRUH];
__device__ float g_h2[N_GRAPHS * GRUH];
__device__ int   g_is64;
// decoupled-lookback scan state + dynamic work counters
__device__ volatile int g_lb_val[NPART];
__device__ volatile int g_lb_flag[NPART];
__device__ int   g_work[4];

__device__ __forceinline__ int load_idx(const void* p, long long i, int is64) {
    return is64 ? (int)((const long long*)p)[i] : ((const int*)p)[i];
}

// ------- init: detect width (per block), zero counters/flags, seed gate bias,
//         x -> fp16, convert weights, count batch sizes — one launch -------
__global__ void init_kernel(const int* __restrict__ ei_raw, const float* __restrict__ gb,
                            const float* __restrict__ x, __half* __restrict__ xh,
                            const void* __restrict__ batch,
                            const float* __restrict__ w0, const float* __restrict__ w1,
                            const float* __restrict__ w2) {
    __shared__ int s_is64;
    if (threadIdx.x < 32) {
        int lane = threadIdx.x;
        int bad = 0;
#pragma unroll
        for (int k = 0; k < 4; k++) bad |= ei_raw[2 * (lane + k * 32) + 1];
        unsigned m = __ballot_sync(0xffffffffu, bad != 0);
        if (lane == 0) {
            s_is64 = (m == 0) ? 1 : 0;
            if (blockIdx.x == 0) g_is64 = s_is64;
        }
    }
    __syncthreads();
    int is64 = s_is64;

    int i = blockIdx.x * blockDim.x + threadIdx.x;
    int stride = gridDim.x * blockDim.x;
    float gbias = gb[0];
    for (int k = i; k < N_NODES; k += stride) {
        g_counts[k] = 0; g_gate[k] = gbias;
    }
    for (int k = i; k < N_GRAPHS; k += stride) g_gcounts[k] = 0;
    for (int k = i; k < NPART; k += stride) { g_lb_flag[k] = 0; g_lb_val[k] = 0; }
    if (i < 4) g_work[i] = 0;
    // batch histogram
    for (int v = i; v < N_NODES; v += stride) {
        int b = load_idx(batch, v, is64);
        atomicAdd(&g_gcounts[b], 1);
    }
    // x (50000x64 fp32) -> fp16
    int total2 = N_NODES * 32;
    const float2* x2 = (const float2*)x;
    __half2* xh2 = (__half2*)xh;
    for (int k = i; k < total2; k += stride) {
        float2 v = x2[k];
        xh2[k] = __floats2half2_rn(v.x, v.y);
    }
    // weights -> fp16 transposed [n][k]
    for (int k = i; k < WTOT; k += stride) {
        const float* B; int K, N, idx;
        if (k < WOFF1)      { B = w0; K = 64;  N = 128; idx = k - WOFF0; }
        else if (k < WOFF2) { B = w1; K = 128; N = 256; idx = k - WOFF1; }
        else                { B = w2; K = 256; N = 512; idx = k - WOFF2; }
        int n = idx / K, kk = idx - n * K;
        g_bwh[k] = __float2half_rn(B[(size_t)kk * N + n]);
    }
}

// ---------- count degrees; record each edge's rank within its dst bucket ----------
__global__ void count_kernel(const void* __restrict__ ei) {
    int is64 = g_is64;
    int i = blockIdx.x * blockDim.x + threadIdx.x;
    int stride = gridDim.x * blockDim.x;
    for (int e = i; e < N_EDGES; e += stride) {
        int d = load_idx(ei, (long long)N_EDGES + e, is64);   // dst = edge_index[1]
        g_rank[e] = atomicAdd(&g_counts[d], 1);
    }
}

// ---- single-pass decoupled-lookback exclusive scan of g_counts -> g_offs
//      (+ fused dinv; block 0 also scans graph offsets) ----
__global__ void __launch_bounds__(256) scan_lookback_kernel() {
    __shared__ int sh[256];
    __shared__ int s_excl;
    int b = blockIdx.x, t = threadIdx.x;
    int i = b * 256 + t;
    int cnt = (i < N_NODES) ? g_counts[i] : 0;
    if (i < N_NODES) g_dinv[i] = rsqrtf((float)(cnt + 1));  // +1 self-loop
    sh[t] = cnt;
    __syncthreads();
    for (int d = 1; d < 256; d <<= 1) {
        int x = (t >= d) ? sh[t - d] : 0;
        __syncthreads();
        sh[t] += x;
        __syncthreads();
    }
    // publish this block's aggregate
    if (t == 0) {
        g_lb_val[b] = sh[255];
        __threadfence();
        g_lb_flag[b] = 1;
    }
    // warp 0: sum all predecessor aggregates (lane-parallel lookback)
    if (t < 32) {
        int sum = 0;
        for (int j = b - 1 - t; j >= 0; j -= 32) {
            while (g_lb_flag[j] == 0) { }
            sum += g_lb_val[j];
        }
#pragma unroll
        for (int o = 16; o > 0; o >>= 1) sum += __shfl_xor_sync(0xffffffffu, sum, o);
        if (t == 0) s_excl = sum;
    }
    __syncthreads();
    int base = s_excl;
    if (i < N_NODES) g_offs[i] = base + sh[t] - cnt;
    if (i == N_NODES - 1) g_offs[N_NODES] = base + sh[t];
    // block 0: exclusive scan of graph counts -> g_goffs
    if (b == 0) {
        __syncthreads();
        int gc = g_gcounts[t];
        sh[t] = gc;
        __syncthreads();
        for (int d = 1; d < 256; d <<= 1) {
            int x = (t >= d) ? sh[t - d] : 0;
            __syncthreads();
            sh[t] += x;
            __syncthreads();
        }
        g_goffs[t] = sh[t] - gc;
        if (t == 255) g_goffs[256] = sh[255];
    }
}

// ---------- CSR fill: atomic-free (uses precomputed ranks) ----------
__global__ void fill_kernel(const void* __restrict__ ei) {
    int is64 = g_is64;
    int i = blockIdx.x * blockDim.x + threadIdx.x;
    int stride = gridDim.x * blockDim.x;
    for (int e = i; e < N_EDGES; e += stride) {
        int d = load_idx(ei, (long long)N_EDGES + e, is64);
        int s = load_idx(ei, e, is64);
        g_csrc[g_offs[d] + g_rank[e]] = s;
    }
}

// --- GCN aggregation; persistent warps, dynamic node assignment (bit-identical per node) ---
__global__ void __launch_bounds__(256) agg64h_kernel(const __half* __restrict__ h,
                                                     __half* __restrict__ out, int wk)
{
    int lane = threadIdx.x & 31;
    while (true) {
        int node;
        if (lane == 0) node = atomicAdd(&g_work[wk], 1);
        node = __shfl_sync(0xffffffffu, node, 0);
        if (node >= N_NODES) return;
        float wd = g_dinv[node];
        float2 acc = __half22float2(*(const __half2*)(h + (size_t)node * 64 + lane * 2));
        float ws = wd * wd;
        acc.x *= ws; acc.y *= ws;
        int e = g_offs[node], e1 = g_offs[node + 1];
        for (; e + 4 <= e1; e += 4) {
            int s0 = g_csrc[e], s1 = g_csrc[e + 1], s2 = g_csrc[e + 2], s3 = g_csrc[e + 3];
            float w0 = g_dinv[s0] * wd, w1 = g_dinv[s1] * wd;
            float w2 = g_dinv[s2] * wd, w3 = g_dinv[s3] * wd;
            float2 v0 = __half22float2(*(const __half2*)(h + (size_t)s0 * 64 + lane * 2));
            float2 v1 = __half22float2(*(const __half2*)(h + (size_t)s1 * 64 + lane * 2));
            float2 v2 = __half22float2(*(const __half2*)(h + (size_t)s2 * 64 + lane * 2));
            float2 v3 = __half22float2(*(const __half2*)(h + (size_t)s3 * 64 + lane * 2));
            acc.x += v0.x * w0 + v1.x * w1 + v2.x * w2 + v3.x * w3;
            acc.y += v0.y * w0 + v1.y * w1 + v2.y * w2 + v3.y * w3;
        }
        for (; e < e1; e++) {
            int s0 = g_csrc[e];
            float w0 = g_dinv[s0] * wd;
            float2 v0 = __half22float2(*(const __half2*)(h + (size_t)s0 * 64 + lane * 2));
            acc.x += v0.x * w0; acc.y += v0.y * w0;
        }
        *(__half2*)(out + (size_t)node * 64 + lane * 2) = __floats2half2_rn(acc.x, acc.y);
    }
}

__global__ void __launch_bounds__(256) agg128h_kernel(const __half* __restrict__ h,
                                                      __half* __restrict__ out, int wk)
{
    int lane = threadIdx.x & 31;
    while (true) {
        int node;
        if (lane == 0) node = atomicAdd(&g_work[wk], 1);
        node = __shfl_sync(0xffffffffu, node, 0);
        if (node >= N_NODES) return;
        float wd = g_dinv[node];
        float acc[4];
        {
            uint2 sv = *(const uint2*)(h + (size_t)node * 128 + lane * 4);
            const __half2* hp = (const __half2*)&sv;
            float ws = wd * wd;
            float2 f0 = __half22float2(hp[0]), f1 = __half22float2(hp[1]);
            acc[0] = f0.x * ws; acc[1] = f0.y * ws; acc[2] = f1.x * ws; acc[3] = f1.y * ws;
        }
        int e = g_offs[node], e1 = g_offs[node + 1];
        for (; e + 4 <= e1; e += 4) {
            int s0 = g_csrc[e], s1 = g_csrc[e + 1], s2 = g_csrc[e + 2], s3 = g_csrc[e + 3];
            float w0 = g_dinv[s0] * wd, w1 = g_dinv[s1] * wd;
            float w2 = g_dinv[s2] * wd, w3 = g_dinv[s3] * wd;
            uint2 v0 = *(const uint2*)(h + (size_t)s0 * 128 + lane * 4);
            uint2 v1 = *(const uint2*)(h + (size_t)s1 * 128 + lane * 4);
            uint2 v2 = *(const uint2*)(h + (size_t)s2 * 128 + lane * 4);
            uint2 v3 = *(const uint2*)(h + (size_t)s3 * 128 + lane * 4);
            const __half2* p0 = (const __half2*)&v0;
            const __half2* p1 = (const __half2*)&v1;
            const __half2* p2 = (const __half2*)&v2;
            const __half2* p3 = (const __half2*)&v3;
#pragma unroll
            for (int q = 0; q < 2; q++) {
                float2 f0 = __half22float2(p0[q]);
                float2 f1 = __half22float2(p1[q]);
                float2 f2 = __half22float2(p2[q]);
                float2 f3 = __half22float2(p3[q]);
                acc[2 * q]     += f0.x * w0 + f1.x * w1 + f2.x * w2 + f3.x * w3;
                acc[2 * q + 1] += f0.y * w0 + f1.y * w1 + f2.y * w2 + f3.y * w3;
            }
        }
        for (; e < e1; e++) {
            int s0 = g_csrc[e];
            float w0 = g_dinv[s0] * wd;
            uint2 v0 = *(const uint2*)(h + (size_t)s0 * 128 + lane * 4);
            const __half2* p0 = (const __half2*)&v0;
#pragma unroll
            for (int q = 0; q < 2; q++) {
                float2 f0 = __half22float2(p0[q]);
                acc[2 * q] += f0.x * w0;
                acc[2 * q + 1] += f0.y * w0;
            }
        }
        __half2 o0 = __floats2half2_rn(acc[0], acc[1]);
        __half2 o1 = __floats2half2_rn(acc[2], acc[3]);
        uint2 ov = make_uint2(*(uint32_t*)&o0, *(uint32_t*)&o1);
        *(uint2*)(out + (size_t)node * 128 + lane * 4) = ov;
    }
}

__global__ void __launch_bounds__(256) agg256h_kernel(const __half* __restrict__ h,
                                                      __half* __restrict__ out, int wk)
{
    int lane = threadIdx.x & 31;
    while (true) {
        int node;
        if (lane == 0) node = atomicAdd(&g_work[wk], 1);
        node = __shfl_sync(0xffffffffu, node, 0);
        if (node >= N_NODES) return;
        float wd = g_dinv[node];
        float acc[8];
        {
            uint4 sv = *(const uint4*)(h + (size_t)node * 256 + lane * 8);
            const __half2* hp = (const __half2*)&sv;
            float ws = wd * wd;
#pragma unroll
            for (int q = 0; q < 4; q++) {
                float2 f = __half22float2(hp[q]);
                acc[2 * q] = f.x * ws;
                acc[2 * q + 1] = f.y * ws;
            }
        }
        int e = g_offs[node], e1 = g_offs[node + 1];
        for (; e + 4 <= e1; e += 4) {
            int s0 = g_csrc[e], s1 = g_csrc[e + 1], s2 = g_csrc[e + 2], s3 = g_csrc[e + 3];
            float w0 = g_dinv[s0] * wd, w1 = g_dinv[s1] * wd;
            float w2 = g_dinv[s2] * wd, w3 = g_dinv[s3] * wd;
            uint4 v0 = *(const uint4*)(h + (size_t)s0 * 256 + lane * 8);
            uint4 v1 = *(const uint4*)(h + (size_t)s1 * 256 + lane * 8);
            uint4 v2 = *(const uint4*)(h + (size_t)s2 * 256 + lane * 8);
            uint4 v3 = *(const uint4*)(h + (size_t)s3 * 256 + lane * 8);
            const __half2* p0 = (const __half2*)&v0;
            const __half2* p1 = (const __half2*)&v1;
            const __half2* p2 = (const __half2*)&v2;
            const __half2* p3 = (const __half2*)&v3;
#pragma unroll
            for (int q = 0; q < 4; q++) {
                float2 f0 = __half22float2(p0[q]);
                float2 f1 = __half22float2(p1[q]);
                float2 f2 = __half22float2(p2[q]);
                float2 f3 = __half22float2(p3[q]);
                acc[2 * q]     += f0.x * w0 + f1.x * w1 + f2.x * w2 + f3.x * w3;
                acc[2 * q + 1] += f0.y * w0 + f1.y * w1 + f2.y * w2 + f3.y * w3;
            }
        }
        for (; e < e1; e++) {
            int n0 = g_csrc[e];
            float w0 = g_dinv[n0] * wd;
            uint4 v0 = *(const uint4*)(h + (size_t)n0 * 256 + lane * 8);
            const __half2* p0 = (const __half2*)&v0;
#pragma unroll
            for (int q = 0; q < 4; q++) {
                float2 f0 = __half22float2(p0[q]);
                acc[2 * q]     += f0.x * w0;
                acc[2 * q + 1] += f0.y * w0;
            }
        }
        __half2 o0 = __floats2half2_rn(acc[0], acc[1]);
        __half2 o1 = __floats2half2_rn(acc[2], acc[3]);
        __half2 o2 = __floats2half2_rn(acc[4], acc[5]);
        __half2 o3 = __floats2half2_rn(acc[6], acc[7]);
        uint4 ov = make_uint4(*(uint32_t*)&o0, *(uint32_t*)&o1, *(uint32_t*)&o2, *(uint32_t*)&o3);
        *(uint4*)(out + (size_t)node * 256 + lane * 8) = ov;
    }
}

// ---------------- fp16 mma ----------------
__device__ __forceinline__ void mma_f16(float* c, const uint32_t* a, const uint32_t* b) {
    asm volatile(
        "mma.sync.aligned.m16n8k16.row.col.f32.f16.f16.f32 "
        "{%0,%1,%2,%3}, {%4,%5,%6,%7}, {%8,%9}, {%0,%1,%2,%3};"
        : "+f"(c[0]), "+f"(c[1]), "+f"(c[2]), "+f"(c[3])
        : "r"(a[0]), "r"(a[1]), "r"(a[2]), "r"(a[3]), "r"(b[0]), "r"(b[1]));
}

// ---- GEMM + bias + ReLU, fp16 operands, fp32 accum; cp.async double-buffered ----
#define HSTR 40

__global__ void __launch_bounds__(256) gemm_f16_kernel(
    const __half* __restrict__ A, const __half* __restrict__ Bh,
    const float* __restrict__ bias,
    __half* __restrict__ Ch, const float* __restrict__ gatew,
    int M, int N, int K)
{
    __shared__ __align__(16) __half As[2][128 * HSTR];
    __shared__ __align__(16) __half Bhs[2][128 * HSTR];
    __shared__ float sgate[128];

    int tid = threadIdx.x;
    int lane = tid & 31;
    int wid = tid >> 5;
    int warp_m = wid >> 2;
    int warp_n = wid & 3;
    int g = lane >> 2;
    int t = lane & 3;
    int row0 = blockIdx.x * 128;
    int col0 = blockIdx.y * 128;

    if (gatew && tid < 128) sgate[tid] = 0.f;

    float acc[4][4][4];
#pragma unroll
    for (int i = 0; i < 4; i++)
#pragma unroll
        for (int j = 0; j < 4; j++)
#pragma unroll
            for (int r = 0; r < 4; r++) acc[i][j][r] = 0.f;

    int f0 = tid, f1 = tid + 256;
    int ar0 = f0 >> 2, ac0 = (f0 & 3) * 8;
    int ar1 = f1 >> 2, ac1 = (f1 & 3) * 8;

    auto issue_tile = [&](int buf, int k0) {
        {
            int grow = row0 + ar0;
            uint32_t dst = (uint32_t)__cvta_generic_to_shared(&As[buf][ar0 * HSTR + ac0]);
            const __half* src = A + (size_t)grow * K + k0 + ac0;
            int p = (grow < M) ? 16 : 0;
            asm volatile("cp.async.cg.shared.global [%0], [%1], 16, %2;"
                         :: "r"(dst), "l"(src), "r"(p));
        }
        {
            int grow = row0 + ar1;
            uint32_t dst = (uint32_t)__cvta_generic_to_shared(&As[buf][ar1 * HSTR + ac1]);
            const __half* src = A + (size_t)grow * K + k0 + ac1;
            int p = (grow < M) ? 16 : 0;
            asm volatile("cp.async.cg.shared.global [%0], [%1], 16, %2;"
                         :: "r"(dst), "l"(src), "r"(p));
        }
        {
            uint32_t dst = (uint32_t)__cvta_generic_to_shared(&Bhs[buf][ar0 * HSTR + ac0]);
            const __half* src = Bh + (size_t)(col0 + ar0) * K + k0 + ac0;
            asm volatile("cp.async.cg.shared.global [%0], [%1], 16;"
                         :: "r"(dst), "l"(src));
        }
        {
            uint32_t dst = (uint32_t)__cvta_generic_to_shared(&Bhs[buf][ar1 * HSTR + ac1]);
            const __half* src = Bh + (size_t)(col0 + ar1) * K + k0 + ac1;
            asm volatile("cp.async.cg.shared.global [%0], [%1], 16;"
                         :: "r"(dst), "l"(src));
        }
        asm volatile("cp.async.commit_group;");
    };

    int nIter = K >> 5;
    issue_tile(0, 0);
    int buf = 0;
    for (int it = 0; it < nIter; it++) {
        if (it + 1 < nIter) {
            issue_tile(buf ^ 1, (it + 1) * 32);
            asm volatile("cp.async.wait_group 1;");
        } else {
            asm volatile("cp.async.wait_group 0;");
        }
        __syncthreads();

        const __half* Ab = As[buf];
        const __half* Bb = Bhs[buf];
#pragma unroll
        for (int kc = 0; kc < 2; kc++) {
            uint32_t bh[4][2];
#pragma unroll
            for (int tn = 0; tn < 4; tn++) {
                int n = warp_n * 32 + tn * 8 + g;
                int base = n * HSTR + kc * 16 + 2 * t;
                bh[tn][0] = *(const uint32_t*)&Bb[base];
                bh[tn][1] = *(const uint32_t*)&Bb[base + 8];
            }
#pragma unroll
            for (int tm = 0; tm < 4; tm++) {
                int row = warp_m * 64 + tm * 16 + g;
                int base = row * HSTR + kc * 16 + 2 * t;
                uint32_t a[4];
                a[0] = *(const uint32_t*)&Ab[base];
                a[1] = *(const uint32_t*)&Ab[base + 8 * HSTR];
                a[2] = *(const uint32_t*)&Ab[base + 8];
                a[3] = *(const uint32_t*)&Ab[base + 8 * HSTR + 8];
#pragma unroll
                for (int tn = 0; tn < 4; tn++) {
                    mma_f16(acc[tm][tn], a, bh[tn]);
                }
            }
        }
        __syncthreads();
        buf ^= 1;
    }

    float bv[4][2], gwv[4][2];
#pragma unroll
    for (int tn = 0; tn < 4; tn++) {
        int col = col0 + warp_n * 32 + tn * 8 + 2 * t;
        bv[tn][0] = bias[col];
        bv[tn][1] = bias[col + 1];
        if (gatew) { gwv[tn][0] = gatew[col]; gwv[tn][1] = gatew[col + 1]; }
    }
#pragma unroll
    for (int tm = 0; tm < 4; tm++) {
        int row = row0 + warp_m * 64 + tm * 16 + g;
        float p0 = 0.f, p1 = 0.f;
#pragma unroll
        for (int tn = 0; tn < 4; tn++) {
            int col = col0 + warp_n * 32 + tn * 8 + 2 * t;
            float v0 = fmaxf(acc[tm][tn][0] + bv[tn][0], 0.f);
            float v1 = fmaxf(acc[tm][tn][1] + bv[tn][1], 0.f);
            float v2 = fmaxf(acc[tm][tn][2] + bv[tn][0], 0.f);
            float v3 = fmaxf(acc[tm][tn][3] + bv[tn][1], 0.f);
            if (row < M)     *(__half2*)(Ch + (size_t)row * N + col)       = __floats2half2_rn(v0, v1);
            if (row + 8 < M) *(__half2*)(Ch + (size_t)(row + 8) * N + col) = __floats2half2_rn(v2, v3);
            if (gatew) {
                p0 += v0 * gwv[tn][0] + v1 * gwv[tn][1];
                p1 += v2 * gwv[tn][0] + v3 * gwv[tn][1];
            }
        }
        if (gatew) {
            p0 += __shfl_xor_sync(0xffffffffu, p0, 1);
            p0 += __shfl_xor_sync(0xffffffffu, p0, 2);
            p1 += __shfl_xor_sync(0xffffffffu, p1, 1);
            p1 += __shfl_xor_sync(0xffffffffu, p1, 2);
            if (t == 0) {
                int rl = warp_m * 64 + tm * 16 + g;
                atomicAdd(&sgate[rl], p0);
                atomicAdd(&sgate[rl + 8], p1);
            }
        }
    }
    if (gatew) {
        __syncthreads();
        if (tid < 128 && row0 + tid < M) atomicAdd(&g_gate[row0 + tid], sgate[tid]);
    }
}

// ------- segment softmax + weighted sum over fp16 x -> graph embeddings [G, 512] -------
__global__ void __launch_bounds__(256) softmax_emb_kernel(const __half* __restrict__ xh)
{
    __shared__ float red[8];
    __shared__ float salpha[256];
    __shared__ float bcast;
    int g = blockIdx.x, tid = threadIdx.x;
    int lane = tid & 31, wid = tid >> 5;
    int s = g_goffs[g], e = g_goffs[g + 1];

    float m = -INFINITY;
    for (int i = s + tid; i < e; i += 256) m = fmaxf(m, g_gate[i]);
#pragma unroll
    for (int o = 16; o > 0; o >>= 1) m = fmaxf(m, __shfl_xor_sync(0xffffffffu, m, o));
    if (lane == 0) red[wid] = m;
    __syncthreads();
    if (wid == 0) {
        float x = (lane < 8) ? red[lane] : -INFINITY;
#pragma unroll
        for (int o = 4; o > 0; o >>= 1) x = fmaxf(x, __shfl_xor_sync(0xffffffffu, x, o));
        if (lane == 0) bcast = x;
    }
    __syncthreads();
    m = bcast;

    float sum = 0.f;
    for (int i = s + tid; i < e; i += 256) sum += expf(g_gate[i] - m);
#pragma unroll
    for (int o = 16; o > 0; o >>= 1) sum += __shfl_xor_sync(0xffffffffu, sum, o);
    if (lane == 0) red[wid] = sum;
    __syncthreads();
    if (wid == 0) {
        float x = (lane < 8) ? red[lane] : 0.f;
#pragma unroll
        for (int o = 4; o > 0; o >>= 1) x += __shfl_xor_sync(0xffffffffu, x, o);
        if (lane == 0) bcast = x;
    }
    __syncthreads();
    float inv = (e > s) ? 1.f / bcast : 0.f;

    float2 acc = make_float2(0.f, 0.f);
    for (int start = s; start < e; start += 256) {
        int i = start + tid;
        salpha[tid] = (i < e) ? expf(g_gate[i] - m) * inv : 0.f;
        __syncthreads();
        int cnt = min(256, e - start);
        const __half2* base = (const __half2*)(xh + (size_t)start * 512);
        for (int k = 0; k < cnt; k++) {
            float a = salpha[k];
            float2 f = __half22float2(base[(size_t)k * 256 + tid]);
            acc.x += f.x * a;
            acc.y += f.y * a;
        }
        __syncthreads();
    }
    g_emb[g * 512 + 2 * tid]     = acc.x;
    g_emb[g * 512 + 2 * tid + 1] = acc.y;
}

// ---- fused GRU layer: h[g,c] = (1-z)*n; gi = A@wih^T (+bih), gh bias = bhh; h0=0 ----
#define GF_BK 32

__global__ void __launch_bounds__(256) gru_fused_kernel(
    const float* __restrict__ A, const float* __restrict__ W,
    const float* __restrict__ bih, const float* __restrict__ bhh,
    float* __restrict__ hout, int K)
{
    __shared__ float As[GF_BK][33];
    __shared__ float Ws[3][16][GF_BK + 1];
    int tid = threadIdx.x;
    int row0 = blockIdx.x * 32;
    int c0 = blockIdx.y * 16;
    int tn = tid & 15, tm = tid >> 4;
    float acc[3][2] = {};

    for (int k0 = 0; k0 < K; k0 += GF_BK) {
#pragma unroll
        for (int l = 0; l < 4; l++) {
            int f = tid + l * 256;
            int r = f >> 5, c = f & 31;
            As[c][r] = A[(size_t)(row0 + r) * K + k0 + c];
        }
#pragma unroll
        for (int l = 0; l < 6; l++) {
            int f = tid + l * 256;
            int gate = f >> 9;
            int rem = f & 511;
            int n = rem >> 5, c = rem & 31;
            Ws[gate][n][c] = W[(size_t)(gate * 256 + c0 + n) * K + k0 + c];
        }
        __syncthreads();
#pragma unroll
        for (int k = 0; k < GF_BK; k++) {
            float a0 = As[k][tm * 2];
            float a1 = As[k][tm * 2 + 1];
            float wr = Ws[0][tn][k], wz = Ws[1][tn][k], wn = Ws[2][tn][k];
            acc[0][0] += a0 * wr; acc[0][1] += a1 * wr;
            acc[1][0] += a0 * wz; acc[1][1] += a1 * wz;
            acc[2][0] += a0 * wn; acc[2][1] += a1 * wn;
        }
        __syncthreads();
    }

    int c = c0 + tn;
    float br = bih[c] + bhh[c];
    float bz = bih[c + 256] + bhh[c + 256];
    float bn_i = bih[c + 512];
    float bn_h = bhh[c + 512];
#pragma unroll
    for (int i = 0; i < 2; i++) {
        int g = row0 + tm * 2 + i;
        float r = 1.f / (1.f + expf(-(acc[0][i] + br)));
        float z = 1.f / (1.f + expf(-(acc[1][i] + bz)));
        float n = tanhf(acc[2][i] + bn_i + r * bn_h);
        hout[g * GRUH + c] = (1.f - z) * n;
    }
}

// ---- projection GEMM: out[G,N] = A[G,K] @ W[N,K]^T + bias; tiles 32x64, BK=32 ----
__global__ void __launch_bounds__(256) proj_gemm_kernel(
    const float* __restrict__ A, const float* __restrict__ W,
    const float* __restrict__ bias, float* __restrict__ C,
    int N, int K)
{
    __shared__ float As[32][33];
    __shared__ float Ws[64][33];
    int tid = threadIdx.x;
    int row0 = blockIdx.x * 32;
    int col0 = blockIdx.y * 64;
    int tn = tid & 15, tm = tid >> 4;
    float acc[2][4] = {};

    for (int k0 = 0; k0 < K; k0 += 32) {
#pragma unroll
        for (int l = 0; l < 4; l++) {
            int f = tid + l * 256;
            int r = f >> 5, c = f & 31;
            As[c][r] = A[(size_t)(row0 + r) * K + k0 + c];
        }
#pragma unroll
        for (int l = 0; l < 8; l++) {
            int f = tid + l * 256;
            int n = f >> 5, c = f & 31;
            Ws[n][c] = W[(size_t)(col0 + n) * K + k0 + c];
        }
        __syncthreads();
#pragma unroll
        for (int k = 0; k < 32; k++) {
            float a0 = As[k][tm * 2];
            float a1 = As[k][tm * 2 + 1];
#pragma unroll
            for (int j = 0; j < 4; j++) {
                float b = Ws[tn * 4 + j][k];
                acc[0][j] += a0 * b;
                acc[1][j] += a1 * b;
            }
        }
        __syncthreads();
    }
#pragma unroll
    for (int i = 0; i < 2; i++) {
        int gg = row0 + tm * 2 + i;
#pragma unroll
        for (int j = 0; j < 4; j++) {
            int nn = col0 + tn * 4 + j;
            C[(size_t)gg * N + nn] = acc[i][j] + bias[nn];
        }
    }
}

// ---------------- launch ----------------
extern "C" void kernel_launch(void* const* d_in, const int* in_sizes, int n_in,
                              void* d_out, int out_size)
{
    const float* x       = (const float*)d_in[0];
    const void*  ei      = d_in[1];
    const void*  batch   = d_in[2];
    const float* w0 = (const float*)d_in[3];  const float* b0 = (const float*)d_in[4];
    const float* w1 = (const float*)d_in[5];  const float* b1 = (const float*)d_in[6];
    const float* w2 = (const float*)d_in[7];  const float* b2 = (const float*)d_in[8];
    const float* gate_w = (const float*)d_in[9];
    const float* gate_b = (const float*)d_in[10];
    const float* wih0 = (const float*)d_in[11];
    const float* bih0 = (const float*)d_in[13];
    const float* bhh0 = (const float*)d_in[14];
    const float* wih1 = (const float*)d_in[15];
    const float* bih1 = (const float*)d_in[17];
    const float* bhh1 = (const float*)d_in[18];
    const float* proj_w = (const float*)d_in[19];
    const float* proj_b = (const float*)d_in[20];
    float* out = (float*)d_out;

    __half *pH, *pA, *pWh;
    float *pEmb, *pH1, *pH2;
    cudaGetSymbolAddress((void**)&pH,   g_hbuf);
    cudaGetSymbolAddress((void**)&pA,   g_abuf);
    cudaGetSymbolAddress((void**)&pWh,  g_bwh);
    cudaGetSymbolAddress((void**)&pEmb, g_emb);
    cudaGetSymbolAddress((void**)&pH1,  g_h1);
    cudaGetSymbolAddress((void**)&pH2,  g_h2);

    // preprocessing
    init_kernel<<<256, 256>>>((const int*)ei, gate_b, x, pH, batch, w0, w1, w2);
    count_kernel<<<1024, 256>>>(ei);
    scan_lookback_kernel<<<NPART, 256>>>();
    fill_kernel<<<1024, 256>>>(ei);

    int gM = (N_NODES + 127) / 128;
    int gAgg = 444;   // persistent CTAs; warps pull nodes dynamically

    // GCN layers (fp16 agg -> fp16 GEMM, cp.async pipelined)
    agg64h_kernel<<<gAgg, 256>>>(pH, pA, 0);
    gemm_f16_kernel<<<dim3(gM, 1), 256>>>(pA, pWh + WOFF0, b0, pH, nullptr,
                                          N_NODES, 128, 64);
    agg128h_kernel<<<gAgg, 256>>>(pH, pA, 1);
    gemm_f16_kernel<<<dim3(gM, 2), 256>>>(pA, pWh + WOFF1, b1, pH, nullptr,
                                          N_NODES, 256, 128);
    agg256h_kernel<<<gAgg, 256>>>(pH, pA, 2);
    gemm_f16_kernel<<<dim3(gM, 4), 256>>>(pA, pWh + WOFF2, b2, pH, gate_w,
                                          N_NODES, 512, 256);

    // attentional aggregation
    softmax_emb_kernel<<<N_GRAPHS, 256>>>(pH);

    // fused GRU layers + projection
    gru_fused_kernel<<<dim3(N_GRAPHS / 32, GRUH / 16), 256>>>(pEmb, wih0, bih0, bhh0, pH1, 512);
    gru_fused_kernel<<<dim3(N_GRAPHS / 32, GRUH / 16), 256>>>(pH1, wih1, bih1, bhh1, pH2, 256);
    proj_gemm_kernel<<<dim3(N_GRAPHS / 32, 512 / 64), 256>>>(pH2, proj_w, proj_b, out, 512, 256);
}

// round 16
// speedup vs baseline: 1.1881x; 1.1881x over previous
#include <cuda_runtime.h>
#include <cuda_fp16.h>
#include <math.h>
#include <stdint.h>

#define N_NODES  50000
#define N_EDGES  800000
#define N_GRAPHS 256
#define DMAX     512
#define GRUH     256
#define NPART    196   // ceil(50000/256)

// weight segments (halves): L0 64x128, L1 128x256, L2 256x512
#define WOFF0 0
#define WOFF1 8192
#define WOFF2 40960
#define WTOT  172032

// ---------------- scratch (device globals; no allocation allowed) ----------------
__device__ __align__(16) __half g_hbuf[(size_t)N_NODES * DMAX];   // layer outputs / xh (fp16)
__device__ __align__(16) __half g_abuf[(size_t)N_NODES * 256];    // agg outputs / GEMM A (fp16)
__device__ __align__(16) __half g_bwh[WTOT];                      // weights fp16, [n][k]
__device__ float g_dinv[N_NODES];
__device__ int   g_counts[N_NODES];
__device__ int   g_rank[N_EDGES];
__device__ int   g_dstv[N_EDGES];
__device__ int   g_offs[N_NODES + 1];
__device__ int   g_csrc[N_EDGES];
__device__ int   g_gcounts[N_GRAPHS];
__device__ int   g_goffs[N_GRAPHS + 1];
__device__ float g_gate[N_NODES];
__device__ __align__(16) float g_emb[N_GRAPHS * 512];
__device__ float g_h1[N_GRAPHS * GRUH];
__device__ float g_h2[N_GRAPHS * GRUH];
__device__ int   g_is64;
// decoupled-lookback scan state
__device__ volatile int g_lb_val[NPART];
__device__ volatile int g_lb_flag[NPART];

__device__ __forceinline__ int load_idx(const void* p, long long i, int is64) {
    return is64 ? (int)((const long long*)p)[i] : ((const int*)p)[i];
}

// ------- init: detect width (per block), zero counters/flags, seed gate bias,
//         x -> fp16, convert weights, count batch sizes — one launch -------
__global__ void init_kernel(const int* __restrict__ ei_raw, const float* __restrict__ gb,
                            const float* __restrict__ x, __half* __restrict__ xh,
                            const void* __restrict__ batch,
                            const float* __restrict__ w0, const float* __restrict__ w1,
                            const float* __restrict__ w2) {
    __shared__ int s_is64;
    if (threadIdx.x < 32) {
        int lane = threadIdx.x;
        int bad = 0;
#pragma unroll
        for (int k = 0; k < 4; k++) bad |= ei_raw[2 * (lane + k * 32) + 1];
        unsigned m = __ballot_sync(0xffffffffu, bad != 0);
        if (lane == 0) {
            s_is64 = (m == 0) ? 1 : 0;
            if (blockIdx.x == 0) g_is64 = s_is64;
        }
    }
    __syncthreads();
    int is64 = s_is64;

    int i = blockIdx.x * blockDim.x + threadIdx.x;
    int stride = gridDim.x * blockDim.x;
    float gbias = gb[0];
    for (int k = i; k < N_NODES; k += stride) {
        g_counts[k] = 0; g_gate[k] = gbias;
    }
    for (int k = i; k < N_GRAPHS; k += stride) g_gcounts[k] = 0;
    for (int k = i; k < NPART; k += stride) { g_lb_flag[k] = 0; g_lb_val[k] = 0; }
    // batch histogram
    for (int v = i; v < N_NODES; v += stride) {
        int b = load_idx(batch, v, is64);
        atomicAdd(&g_gcounts[b], 1);
    }
    // x (50000x64 fp32) -> fp16
    int total2 = N_NODES * 32;
    const float2* x2 = (const float2*)x;
    __half2* xh2 = (__half2*)xh;
    for (int k = i; k < total2; k += stride) {
        float2 v = x2[k];
        xh2[k] = __floats2half2_rn(v.x, v.y);
    }
    // weights -> fp16 transposed [n][k]
    for (int k = i; k < WTOT; k += stride) {
        const float* B; int K, N, idx;
        if (k < WOFF1)      { B = w0; K = 64;  N = 128; idx = k - WOFF0; }
        else if (k < WOFF2) { B = w1; K = 128; N = 256; idx = k - WOFF1; }
        else                { B = w2; K = 256; N = 512; idx = k - WOFF2; }
        int n = idx / K, kk = idx - n * K;
        g_bwh[k] = __float2half_rn(B[(size_t)kk * N + n]);
    }
}

// ---- count degrees; record edge rank within dst bucket + cache decoded dst ----
__global__ void count_kernel(const void* __restrict__ ei) {
    int is64 = g_is64;
    int i = blockIdx.x * blockDim.x + threadIdx.x;
    int stride = gridDim.x * blockDim.x;
    for (int e = i; e < N_EDGES; e += stride) {
        int d = load_idx(ei, (long long)N_EDGES + e, is64);   // dst = edge_index[1]
        g_dstv[e] = d;
        g_rank[e] = atomicAdd(&g_counts[d], 1);
    }
}

// ---- single-pass decoupled-lookback exclusive scan of g_counts -> g_offs
//      (+ fused dinv; block 0 also scans graph offsets) ----
__global__ void __launch_bounds__(256) scan_lookback_kernel() {
    __shared__ int sh[256];
    __shared__ int s_excl;
    int b = blockIdx.x, t = threadIdx.x;
    int i = b * 256 + t;
    int cnt = (i < N_NODES) ? g_counts[i] : 0;
    if (i < N_NODES) g_dinv[i] = rsqrtf((float)(cnt + 1));  // +1 self-loop
    sh[t] = cnt;
    __syncthreads();
    for (int d = 1; d < 256; d <<= 1) {
        int x = (t >= d) ? sh[t - d] : 0;
        __syncthreads();
        sh[t] += x;
        __syncthreads();
    }
    if (t == 0) {
        g_lb_val[b] = sh[255];
        __threadfence();
        g_lb_flag[b] = 1;
    }
    if (t < 32) {
        int sum = 0;
        for (int j = b - 1 - t; j >= 0; j -= 32) {
            while (g_lb_flag[j] == 0) { }
            sum += g_lb_val[j];
        }
#pragma unroll
        for (int o = 16; o > 0; o >>= 1) sum += __shfl_xor_sync(0xffffffffu, sum, o);
        if (t == 0) s_excl = sum;
    }
    __syncthreads();
    int base = s_excl;
    if (i < N_NODES) g_offs[i] = base + sh[t] - cnt;
    if (i == N_NODES - 1) g_offs[N_NODES] = base + sh[t];
    if (b == 0) {
        __syncthreads();
        int gc = g_gcounts[t];
        sh[t] = gc;
        __syncthreads();
        for (int d = 1; d < 256; d <<= 1) {
            int x = (t >= d) ? sh[t - d] : 0;
            __syncthreads();
            sh[t] += x;
            __syncthreads();
        }
        g_goffs[t] = sh[t] - gc;
        if (t == 255) g_goffs[256] = sh[255];
    }
}

// ---------- CSR fill: atomic-free (precomputed ranks + cached dst ids) ----------
__global__ void fill_kernel(const void* __restrict__ ei) {
    int is64 = g_is64;
    int i = blockIdx.x * blockDim.x + threadIdx.x;
    int stride = gridDim.x * blockDim.x;
    for (int e = i; e < N_EDGES; e += stride) {
        int d = g_dstv[e];
        int s = load_idx(ei, e, is64);
        g_csrc[g_offs[d] + g_rank[e]] = s;
    }
}

// ------------- GCN aggregation; static warp-per-node; fp16 in/out; MLP=4 -------------
__global__ void __launch_bounds__(256) agg64h_kernel(const __half* __restrict__ h,
                                                     __half* __restrict__ out)
{
    int node = blockIdx.x * 8 + (threadIdx.x >> 5);
    if (node >= N_NODES) return;
    int lane = threadIdx.x & 31;
    float wd = g_dinv[node];
    float2 acc = __half22float2(*(const __half2*)(h + (size_t)node * 64 + lane * 2));
    float ws = wd * wd;
    acc.x *= ws; acc.y *= ws;
    int e = g_offs[node], e1 = g_offs[node + 1];
    for (; e + 4 <= e1; e += 4) {
        int s0 = g_csrc[e], s1 = g_csrc[e + 1], s2 = g_csrc[e + 2], s3 = g_csrc[e + 3];
        float w0 = g_dinv[s0] * wd, w1 = g_dinv[s1] * wd;
        float w2 = g_dinv[s2] * wd, w3 = g_dinv[s3] * wd;
        float2 v0 = __half22float2(*(const __half2*)(h + (size_t)s0 * 64 + lane * 2));
        float2 v1 = __half22float2(*(const __half2*)(h + (size_t)s1 * 64 + lane * 2));
        float2 v2 = __half22float2(*(const __half2*)(h + (size_t)s2 * 64 + lane * 2));
        float2 v3 = __half22float2(*(const __half2*)(h + (size_t)s3 * 64 + lane * 2));
        acc.x += v0.x * w0 + v1.x * w1 + v2.x * w2 + v3.x * w3;
        acc.y += v0.y * w0 + v1.y * w1 + v2.y * w2 + v3.y * w3;
    }
    for (; e < e1; e++) {
        int s0 = g_csrc[e];
        float w0 = g_dinv[s0] * wd;
        float2 v0 = __half22float2(*(const __half2*)(h + (size_t)s0 * 64 + lane * 2));
        acc.x += v0.x * w0; acc.y += v0.y * w0;
    }
    *(__half2*)(out + (size_t)node * 64 + lane * 2) = __floats2half2_rn(acc.x, acc.y);
}

__global__ void __launch_bounds__(256) agg128h_kernel(const __half* __restrict__ h,
                                                      __half* __restrict__ out)
{
    int node = blockIdx.x * 8 + (threadIdx.x >> 5);
    if (node >= N_NODES) return;
    int lane = threadIdx.x & 31;
    float wd = g_dinv[node];
    float acc[4];
    {
        uint2 sv = *(const uint2*)(h + (size_t)node * 128 + lane * 4);
        const __half2* hp = (const __half2*)&sv;
        float ws = wd * wd;
        float2 f0 = __half22float2(hp[0]), f1 = __half22float2(hp[1]);
        acc[0] = f0.x * ws; acc[1] = f0.y * ws; acc[2] = f1.x * ws; acc[3] = f1.y * ws;
    }
    int e = g_offs[node], e1 = g_offs[node + 1];
    for (; e + 4 <= e1; e += 4) {
        int s0 = g_csrc[e], s1 = g_csrc[e + 1], s2 = g_csrc[e + 2], s3 = g_csrc[e + 3];
        float w0 = g_dinv[s0] * wd, w1 = g_dinv[s1] * wd;
        float w2 = g_dinv[s2] * wd, w3 = g_dinv[s3] * wd;
        uint2 v0 = *(const uint2*)(h + (size_t)s0 * 128 + lane * 4);
        uint2 v1 = *(const uint2*)(h + (size_t)s1 * 128 + lane * 4);
        uint2 v2 = *(const uint2*)(h + (size_t)s2 * 128 + lane * 4);
        uint2 v3 = *(const uint2*)(h + (size_t)s3 * 128 + lane * 4);
        const __half2* p0 = (const __half2*)&v0;
        const __half2* p1 = (const __half2*)&v1;
        const __half2* p2 = (const __half2*)&v2;
        const __half2* p3 = (const __half2*)&v3;
#pragma unroll
        for (int q = 0; q < 2; q++) {
            float2 f0 = __half22float2(p0[q]);
            float2 f1 = __half22float2(p1[q]);
            float2 f2 = __half22float2(p2[q]);
            float2 f3 = __half22float2(p3[q]);
            acc[2 * q]     += f0.x * w0 + f1.x * w1 + f2.x * w2 + f3.x * w3;
            acc[2 * q + 1] += f0.y * w0 + f1.y * w1 + f2.y * w2 + f3.y * w3;
        }
    }
    for (; e < e1; e++) {
        int s0 = g_csrc[e];
        float w0 = g_dinv[s0] * wd;
        uint2 v0 = *(const uint2*)(h + (size_t)s0 * 128 + lane * 4);
        const __half2* p0 = (const __half2*)&v0;
#pragma unroll
        for (int q = 0; q < 2; q++) {
            float2 f0 = __half22float2(p0[q]);
            acc[2 * q] += f0.x * w0;
            acc[2 * q + 1] += f0.y * w0;
        }
    }
    __half2 o0 = __floats2half2_rn(acc[0], acc[1]);
    __half2 o1 = __floats2half2_rn(acc[2], acc[3]);
    uint2 ov = make_uint2(*(uint32_t*)&o0, *(uint32_t*)&o1);
    *(uint2*)(out + (size_t)node * 128 + lane * 4) = ov;
}

__global__ void __launch_bounds__(256) agg256h_kernel(const __half* __restrict__ h,
                                                      __half* __restrict__ out)
{
    int node = blockIdx.x * 8 + (threadIdx.x >> 5);
    if (node >= N_NODES) return;
    int lane = threadIdx.x & 31;
    float wd = g_dinv[node];
    float acc[8];
    {
        uint4 sv = *(const uint4*)(h + (size_t)node * 256 + lane * 8);
        const __half2* hp = (const __half2*)&sv;
        float ws = wd * wd;
#pragma unroll
        for (int q = 0; q < 4; q++) {
            float2 f = __half22float2(hp[q]);
            acc[2 * q] = f.x * ws;
            acc[2 * q + 1] = f.y * ws;
        }
    }
    int e = g_offs[node], e1 = g_offs[node + 1];
    for (; e + 4 <= e1; e += 4) {
        int s0 = g_csrc[e], s1 = g_csrc[e + 1], s2 = g_csrc[e + 2], s3 = g_csrc[e + 3];
        float w0 = g_dinv[s0] * wd, w1 = g_dinv[s1] * wd;
        float w2 = g_dinv[s2] * wd, w3 = g_dinv[s3] * wd;
        uint4 v0 = *(const uint4*)(h + (size_t)s0 * 256 + lane * 8);
        uint4 v1 = *(const uint4*)(h + (size_t)s1 * 256 + lane * 8);
        uint4 v2 = *(const uint4*)(h + (size_t)s2 * 256 + lane * 8);
        uint4 v3 = *(const uint4*)(h + (size_t)s3 * 256 + lane * 8);
        const __half2* p0 = (const __half2*)&v0;
        const __half2* p1 = (const __half2*)&v1;
        const __half2* p2 = (const __half2*)&v2;
        const __half2* p3 = (const __half2*)&v3;
#pragma unroll
        for (int q = 0; q < 4; q++) {
            float2 f0 = __half22float2(p0[q]);
            float2 f1 = __half22float2(p1[q]);
            float2 f2 = __half22float2(p2[q]);
            float2 f3 = __half22float2(p3[q]);
            acc[2 * q]     += f0.x * w0 + f1.x * w1 + f2.x * w2 + f3.x * w3;
            acc[2 * q + 1] += f0.y * w0 + f1.y * w1 + f2.y * w2 + f3.y * w3;
        }
    }
    for (; e < e1; e++) {
        int n0 = g_csrc[e];
        float w0 = g_dinv[n0] * wd;
        uint4 v0 = *(const uint4*)(h + (size_t)n0 * 256 + lane * 8);
        const __half2* p0 = (const __half2*)&v0;
#pragma unroll
        for (int q = 0; q < 4; q++) {
            float2 f0 = __half22float2(p0[q]);
            acc[2 * q]     += f0.x * w0;
            acc[2 * q + 1] += f0.y * w0;
        }
    }
    __half2 o0 = __floats2half2_rn(acc[0], acc[1]);
    __half2 o1 = __floats2half2_rn(acc[2], acc[3]);
    __half2 o2 = __floats2half2_rn(acc[4], acc[5]);
    __half2 o3 = __floats2half2_rn(acc[6], acc[7]);
    uint4 ov = make_uint4(*(uint32_t*)&o0, *(uint32_t*)&o1, *(uint32_t*)&o2, *(uint32_t*)&o3);
    *(uint4*)(out + (size_t)node * 256 + lane * 8) = ov;
}

// ---------------- fp16 mma ----------------
__device__ __forceinline__ void mma_f16(float* c, const uint32_t* a, const uint32_t* b) {
    asm volatile(
        "mma.sync.aligned.m16n8k16.row.col.f32.f16.f16.f32 "
        "{%0,%1,%2,%3}, {%4,%5,%6,%7}, {%8,%9}, {%0,%1,%2,%3};"
        : "+f"(c[0]), "+f"(c[1]), "+f"(c[2]), "+f"(c[3])
        : "r"(a[0]), "r"(a[1]), "r"(a[2]), "r"(a[3]), "r"(b[0]), "r"(b[1]));
}

// ---- GEMM + bias + ReLU, fp16 operands, fp32 accum; cp.async double-buffered ----
#define HSTR 40

__global__ void __launch_bounds__(256) gemm_f16_kernel(
    const __half* __restrict__ A, const __half* __restrict__ Bh,
    const float* __restrict__ bias,
    __half* __restrict__ Ch, const float* __restrict__ gatew,
    int M, int N, int K)
{
    __shared__ __align__(16) __half As[2][128 * HSTR];
    __shared__ __align__(16) __half Bhs[2][128 * HSTR];
    __shared__ float sgate[128];

    int tid = threadIdx.x;
    int lane = tid & 31;
    int wid = tid >> 5;
    int warp_m = wid >> 2;
    int warp_n = wid & 3;
    int g = lane >> 2;
    int t = lane & 3;
    int row0 = blockIdx.x * 128;
    int col0 = blockIdx.y * 128;

    if (gatew && tid < 128) sgate[tid] = 0.f;

    float acc[4][4][4];
#pragma unroll
    for (int i = 0; i < 4; i++)
#pragma unroll
        for (int j = 0; j < 4; j++)
#pragma unroll
            for (int r = 0; r < 4; r++) acc[i][j][r] = 0.f;

    int f0 = tid, f1 = tid + 256;
    int ar0 = f0 >> 2, ac0 = (f0 & 3) * 8;
    int ar1 = f1 >> 2, ac1 = (f1 & 3) * 8;

    auto issue_tile = [&](int buf, int k0) {
        {
            int grow = row0 + ar0;
            uint32_t dst = (uint32_t)__cvta_generic_to_shared(&As[buf][ar0 * HSTR + ac0]);
            const __half* src = A + (size_t)grow * K + k0 + ac0;
            int p = (grow < M) ? 16 : 0;
            asm volatile("cp.async.cg.shared.global [%0], [%1], 16, %2;"
                         :: "r"(dst), "l"(src), "r"(p));
        }
        {
            int grow = row0 + ar1;
            uint32_t dst = (uint32_t)__cvta_generic_to_shared(&As[buf][ar1 * HSTR + ac1]);
            const __half* src = A + (size_t)grow * K + k0 + ac1;
            int p = (grow < M) ? 16 : 0;
            asm volatile("cp.async.cg.shared.global [%0], [%1], 16, %2;"
                         :: "r"(dst), "l"(src), "r"(p));
        }
        {
            uint32_t dst = (uint32_t)__cvta_generic_to_shared(&Bhs[buf][ar0 * HSTR + ac0]);
            const __half* src = Bh + (size_t)(col0 + ar0) * K + k0 + ac0;
            asm volatile("cp.async.cg.shared.global [%0], [%1], 16;"
                         :: "r"(dst), "l"(src));
        }
        {
            uint32_t dst = (uint32_t)__cvta_generic_to_shared(&Bhs[buf][ar1 * HSTR + ac1]);
            const __half* src = Bh + (size_t)(col0 + ar1) * K + k0 + ac1;
            asm volatile("cp.async.cg.shared.global [%0], [%1], 16;"
                         :: "r"(dst), "l"(src));
        }
        asm volatile("cp.async.commit_group;");
    };

    int nIter = K >> 5;
    issue_tile(0, 0);
    int buf = 0;
    for (int it = 0; it < nIter; it++) {
        if (it + 1 < nIter) {
            issue_tile(buf ^ 1, (it + 1) * 32);
            asm volatile("cp.async.wait_group 1;");
        } else {
            asm volatile("cp.async.wait_group 0;");
        }
        __syncthreads();

        const __half* Ab = As[buf];
        const __half* Bb = Bhs[buf];
#pragma unroll
        for (int kc = 0; kc < 2; kc++) {
            uint32_t bh[4][2];
#pragma unroll
            for (int tn = 0; tn < 4; tn++) {
                int n = warp_n * 32 + tn * 8 + g;
                int base = n * HSTR + kc * 16 + 2 * t;
                bh[tn][0] = *(const uint32_t*)&Bb[base];
                bh[tn][1] = *(const uint32_t*)&Bb[base + 8];
            }
#pragma unroll
            for (int tm = 0; tm < 4; tm++) {
                int row = warp_m * 64 + tm * 16 + g;
                int base = row * HSTR + kc * 16 + 2 * t;
                uint32_t a[4];
                a[0] = *(const uint32_t*)&Ab[base];
                a[1] = *(const uint32_t*)&Ab[base + 8 * HSTR];
                a[2] = *(const uint32_t*)&Ab[base + 8];
                a[3] = *(const uint32_t*)&Ab[base + 8 * HSTR + 8];
#pragma unroll
                for (int tn = 0; tn < 4; tn++) {
                    mma_f16(acc[tm][tn], a, bh[tn]);
                }
            }
        }
        __syncthreads();
        buf ^= 1;
    }

    float bv[4][2], gwv[4][2];
#pragma unroll
    for (int tn = 0; tn < 4; tn++) {
        int col = col0 + warp_n * 32 + tn * 8 + 2 * t;
        bv[tn][0] = bias[col];
        bv[tn][1] = bias[col + 1];
        if (gatew) { gwv[tn][0] = gatew[col]; gwv[tn][1] = gatew[col + 1]; }
    }
#pragma unroll
    for (int tm = 0; tm < 4; tm++) {
        int row = row0 + warp_m * 64 + tm * 16 + g;
        float p0 = 0.f, p1 = 0.f;
#pragma unroll
        for (int tn = 0; tn < 4; tn++) {
            int col = col0 + warp_n * 32 + tn * 8 + 2 * t;
            float v0 = fmaxf(acc[tm][tn][0] + bv[tn][0], 0.f);
            float v1 = fmaxf(acc[tm][tn][1] + bv[tn][1], 0.f);
            float v2 = fmaxf(acc[tm][tn][2] + bv[tn][0], 0.f);
            float v3 = fmaxf(acc[tm][tn][3] + bv[tn][1], 0.f);
            if (row < M)     *(__half2*)(Ch + (size_t)row * N + col)       = __floats2half2_rn(v0, v1);
            if (row + 8 < M) *(__half2*)(Ch + (size_t)(row + 8) * N + col) = __floats2half2_rn(v2, v3);
            if (gatew) {
                p0 += v0 * gwv[tn][0] + v1 * gwv[tn][1];
                p1 += v2 * gwv[tn][0] + v3 * gwv[tn][1];
            }
        }
        if (gatew) {
            p0 += __shfl_xor_sync(0xffffffffu, p0, 1);
            p0 += __shfl_xor_sync(0xffffffffu, p0, 2);
            p1 += __shfl_xor_sync(0xffffffffu, p1, 1);
            p1 += __shfl_xor_sync(0xffffffffu, p1, 2);
            if (t == 0) {
                int rl = warp_m * 64 + tm * 16 + g;
                atomicAdd(&sgate[rl], p0);
                atomicAdd(&sgate[rl + 8], p1);
            }
        }
    }
    if (gatew) {
        __syncthreads();
        if (tid < 128 && row0 + tid < M) atomicAdd(&g_gate[row0 + tid], sgate[tid]);
    }
}

// ------- segment softmax + weighted sum over fp16 x -> graph embeddings [G, 512] -------
__global__ void __launch_bounds__(256) softmax_emb_kernel(const __half* __restrict__ xh)
{
    __shared__ float red[8];
    __shared__ float salpha[256];
    __shared__ float bcast;
    int g = blockIdx.x, tid = threadIdx.x;
    int lane = tid & 31, wid = tid >> 5;
    int s = g_goffs[g], e = g_goffs[g + 1];

    float m = -INFINITY;
    for (int i = s + tid; i < e; i += 256) m = fmaxf(m, g_gate[i]);
#pragma unroll
    for (int o = 16; o > 0; o >>= 1) m = fmaxf(m, __shfl_xor_sync(0xffffffffu, m, o));
    if (lane == 0) red[wid] = m;
    __syncthreads();
    if (wid == 0) {
        float x = (lane < 8) ? red[lane] : -INFINITY;
#pragma unroll
        for (int o = 4; o > 0; o >>= 1) x = fmaxf(x, __shfl_xor_sync(0xffffffffu, x, o));
        if (lane == 0) bcast = x;
    }
    __syncthreads();
    m = bcast;

    float sum = 0.f;
    for (int i = s + tid; i < e; i += 256) sum += expf(g_gate[i] - m);
#pragma unroll
    for (int o = 16; o > 0; o >>= 1) sum += __shfl_xor_sync(0xffffffffu, sum, o);
    if (lane == 0) red[wid] = sum;
    __syncthreads();
    if (wid == 0) {
        float x = (lane < 8) ? red[lane] : 0.f;
#pragma unroll
        for (int o = 4; o > 0; o >>= 1) x += __shfl_xor_sync(0xffffffffu, x, o);
        if (lane == 0) bcast = x;
    }
    __syncthreads();
    float inv = (e > s) ? 1.f / bcast : 0.f;

    float2 acc = make_float2(0.f, 0.f);
    for (int start = s; start < e; start += 256) {
        int i = start + tid;
        salpha[tid] = (i < e) ? expf(g_gate[i] - m) * inv : 0.f;
        __syncthreads();
        int cnt = min(256, e - start);
        const __half2* base = (const __half2*)(xh + (size_t)start * 512);
        for (int k = 0; k < cnt; k++) {
            float a = salpha[k];
            float2 f = __half22float2(base[(size_t)k * 256 + tid]);
            acc.x += f.x * a;
            acc.y += f.y * a;
        }
        __syncthreads();
    }
    g_emb[g * 512 + 2 * tid]     = acc.x;
    g_emb[g * 512 + 2 * tid + 1] = acc.y;
}

// ---- fused GRU layer: h[g,c] = (1-z)*n; gi = A@wih^T (+bih), gh bias = bhh; h0=0 ----
#define GF_BK 32

__global__ void __launch_bounds__(256) gru_fused_kernel(
    const float* __restrict__ A, const float* __restrict__ W,
    const float* __restrict__ bih, const float* __restrict__ bhh,
    float* __restrict__ hout, int K)
{
    __shared__ float As[GF_BK][33];
    __shared__ float Ws[3][16][GF_BK + 1];
    int tid = threadIdx.x;
    int row0 = blockIdx.x * 32;
    int c0 = blockIdx.y * 16;
    int tn = tid & 15, tm = tid >> 4;
    float acc[3][2] = {};

    for (int k0 = 0; k0 < K; k0 += GF_BK) {
#pragma unroll
        for (int l = 0; l < 4; l++) {
            int f = tid + l * 256;
            int r = f >> 5, c = f & 31;
            As[c][r] = A[(size_t)(row0 + r) * K + k0 + c];
        }
#pragma unroll
        for (int l = 0; l < 6; l++) {
            int f = tid + l * 256;
            int gate = f >> 9;
            int rem = f & 511;
            int n = rem >> 5, c = rem & 31;
            Ws[gate][n][c] = W[(size_t)(gate * 256 + c0 + n) * K + k0 + c];
        }
        __syncthreads();
#pragma unroll
        for (int k = 0; k < GF_BK; k++) {
            float a0 = As[k][tm * 2];
            float a1 = As[k][tm * 2 + 1];
            float wr = Ws[0][tn][k], wz = Ws[1][tn][k], wn = Ws[2][tn][k];
            acc[0][0] += a0 * wr; acc[0][1] += a1 * wr;
            acc[1][0] += a0 * wz; acc[1][1] += a1 * wz;
            acc[2][0] += a0 * wn; acc[2][1] += a1 * wn;
        }
        __syncthreads();
    }

    int c = c0 + tn;
    float br = bih[c] + bhh[c];
    float bz = bih[c + 256] + bhh[c + 256];
    float bn_i = bih[c + 512];
    float bn_h = bhh[c + 512];
#pragma unroll
    for (int i = 0; i < 2; i++) {
        int g = row0 + tm * 2 + i;
        float r = 1.f / (1.f + expf(-(acc[0][i] + br)));
        float z = 1.f / (1.f + expf(-(acc[1][i] + bz)));
        float n = tanhf(acc[2][i] + bn_i + r * bn_h);
        hout[g * GRUH + c] = (1.f - z) * n;
    }
}

// ---- projection GEMM: out[G,N] = A[G,K] @ W[N,K]^T + bias; tiles 32x64, BK=32 ----
__global__ void __launch_bounds__(256) proj_gemm_kernel(
    const float* __restrict__ A, const float* __restrict__ W,
    const float* __restrict__ bias, float* __restrict__ C,
    int N, int K)
{
    __shared__ float As[32][33];
    __shared__ float Ws[64][33];
    int tid = threadIdx.x;
    int row0 = blockIdx.x * 32;
    int col0 = blockIdx.y * 64;
    int tn = tid & 15, tm = tid >> 4;
    float acc[2][4] = {};

    for (int k0 = 0; k0 < K; k0 += 32) {
#pragma unroll
        for (int l = 0; l < 4; l++) {
            int f = tid + l * 256;
            int r = f >> 5, c = f & 31;
            As[c][r] = A[(size_t)(row0 + r) * K + k0 + c];
        }
#pragma unroll
        for (int l = 0; l < 8; l++) {
            int f = tid + l * 256;
            int n = f >> 5, c = f & 31;
            Ws[n][c] = W[(size_t)(col0 + n) * K + k0 + c];
        }
        __syncthreads();
#pragma unroll
        for (int k = 0; k < 32; k++) {
            float a0 = As[k][tm * 2];
            float a1 = As[k][tm * 2 + 1];
#pragma unroll
            for (int j = 0; j < 4; j++) {
                float b = Ws[tn * 4 + j][k];
                acc[0][j] += a0 * b;
                acc[1][j] += a1 * b;
            }
        }
        __syncthreads();
    }
#pragma unroll
    for (int i = 0; i < 2; i++) {
        int gg = row0 + tm * 2 + i;
#pragma unroll
        for (int j = 0; j < 4; j++) {
            int nn = col0 + tn * 4 + j;
            C[(size_t)gg * N + nn] = acc[i][j] + bias[nn];
        }
    }
}

// ---------------- launch ----------------
extern "C" void kernel_launch(void* const* d_in, const int* in_sizes, int n_in,
                              void* d_out, int out_size)
{
    const float* x       = (const float*)d_in[0];
    const void*  ei      = d_in[1];
    const void*  batch   = d_in[2];
    const float* w0 = (const float*)d_in[3];  const float* b0 = (const float*)d_in[4];
    const float* w1 = (const float*)d_in[5];  const float* b1 = (const float*)d_in[6];
    const float* w2 = (const float*)d_in[7];  const float* b2 = (const float*)d_in[8];
    const float* gate_w = (const float*)d_in[9];
    const float* gate_b = (const float*)d_in[10];
    const float* wih0 = (const float*)d_in[11];
    const float* bih0 = (const float*)d_in[13];
    const float* bhh0 = (const float*)d_in[14];
    const float* wih1 = (const float*)d_in[15];
    const float* bih1 = (const float*)d_in[17];
    const float* bhh1 = (const float*)d_in[18];
    const float* proj_w = (const float*)d_in[19];
    const float* proj_b = (const float*)d_in[20];
    float* out = (float*)d_out;

    __half *pH, *pA, *pWh;
    float *pEmb, *pH1, *pH2;
    cudaGetSymbolAddress((void**)&pH,   g_hbuf);
    cudaGetSymbolAddress((void**)&pA,   g_abuf);
    cudaGetSymbolAddress((void**)&pWh,  g_bwh);
    cudaGetSymbolAddress((void**)&pEmb, g_emb);
    cudaGetSymbolAddress((void**)&pH1,  g_h1);
    cudaGetSymbolAddress((void**)&pH2,  g_h2);

    // preprocessing
    init_kernel<<<256, 256>>>((const int*)ei, gate_b, x, pH, batch, w0, w1, w2);
    count_kernel<<<1024, 256>>>(ei);
    scan_lookback_kernel<<<NPART, 256>>>();
    fill_kernel<<<1024, 256>>>(ei);

    int gM = (N_NODES + 127) / 128;
    int gAgg = (N_NODES + 7) / 8;

    // GCN layers (fp16 agg -> fp16 GEMM, cp.async pipelined)
    agg64h_kernel<<<gAgg, 256>>>(pH, pA);
    gemm_f16_kernel<<<dim3(gM, 1), 256>>>(pA, pWh + WOFF0, b0, pH, nullptr,
                                          N_NODES, 128, 64);
    agg128h_kernel<<<gAgg, 256>>>(pH, pA);
    gemm_f16_kernel<<<dim3(gM, 2), 256>>>(pA, pWh + WOFF1, b1, pH, nullptr,
                                          N_NODES, 256, 128);
    agg256h_kernel<<<gAgg, 256>>>(pH, pA);
    gemm_f16_kernel<<<dim3(gM, 4), 256>>>(pA, pWh + WOFF2, b2, pH, gate_w,
                                          N_NODES, 512, 256);

    // attentional aggregation
    softmax_emb_kernel<<<N_GRAPHS, 256>>>(pH);

    // fused GRU layers + projection
    gru_fused_kernel<<<dim3(N_GRAPHS / 32, GRUH / 16), 256>>>(pEmb, wih0, bih0, bhh0, pH1, 512);
    gru_fused_kernel<<<dim3(N_GRAPHS / 32, GRUH / 16), 256>>>(pH1, wih1, bih1, bhh1, pH2, 256);
    proj_gemm_kernel<<<dim3(N_GRAPHS / 32, 512 / 64), 256>>>(pH2, proj_w, proj_b, out, 512, 256);
}

// round 17
// speedup vs baseline: 1.2212x; 1.0278x over previous
#include <cuda_runtime.h>
#include <cuda_fp16.h>
#include <math.h>
#include <stdint.h>

#define N_NODES  50000
#define N_EDGES  800000
#define N_GRAPHS 256
#define DMAX     512
#define GRUH     256
#define NPART    196   // ceil(50000/256)

// weight segments (halves): L0 64x128, L1 128x256, L2 256x512
#define WOFF0 0
#define WOFF1 8192
#define WOFF2 40960
#define WTOT  172032

// ---------------- scratch (device globals; no allocation allowed) ----------------
__device__ __align__(16) __half g_hbuf[(size_t)N_NODES * DMAX];   // layer outputs / xh (fp16)
__device__ __align__(16) __half g_abuf[(size_t)N_NODES * 256];    // agg outputs / GEMM A (fp16)
__device__ __align__(16) __half g_bwh[WTOT];                      // weights fp16, [n][k]
__device__ float g_dinv[N_NODES];
__device__ int   g_counts[N_NODES];
__device__ int   g_rank[N_EDGES];
__device__ int   g_dstv[N_EDGES];
__device__ int   g_offs[N_NODES + 1];
__device__ int   g_csrc[N_EDGES];
__device__ __align__(16) float g_wedge[N_EDGES];   // per-edge weight dinv[s]*dinv[d], CSR order
__device__ int   g_gcounts[N_GRAPHS];
__device__ int   g_goffs[N_GRAPHS + 1];
__device__ float g_gate[N_NODES];
__device__ __align__(16) float g_emb[N_GRAPHS * 512];
__device__ float g_h1[N_GRAPHS * GRUH];
__device__ float g_h2[N_GRAPHS * GRUH];
__device__ int   g_is64;
// decoupled-lookback scan state
__device__ volatile int g_lb_val[NPART];
__device__ volatile int g_lb_flag[NPART];

__device__ __forceinline__ int load_idx(const void* p, long long i, int is64) {
    return is64 ? (int)((const long long*)p)[i] : ((const int*)p)[i];
}

// ------- init: detect width (per block), zero counters/flags, seed gate bias,
//         x -> fp16, convert weights, count batch sizes — one launch -------
__global__ void init_kernel(const int* __restrict__ ei_raw, const float* __restrict__ gb,
                            const float* __restrict__ x, __half* __restrict__ xh,
                            const void* __restrict__ batch,
                            const float* __restrict__ w0, const float* __restrict__ w1,
                            const float* __restrict__ w2) {
    __shared__ int s_is64;
    if (threadIdx.x < 32) {
        int lane = threadIdx.x;
        int bad = 0;
#pragma unroll
        for (int k = 0; k < 4; k++) bad |= ei_raw[2 * (lane + k * 32) + 1];
        unsigned m = __ballot_sync(0xffffffffu, bad != 0);
        if (lane == 0) {
            s_is64 = (m == 0) ? 1 : 0;
            if (blockIdx.x == 0) g_is64 = s_is64;
        }
    }
    __syncthreads();
    int is64 = s_is64;

    int i = blockIdx.x * blockDim.x + threadIdx.x;
    int stride = gridDim.x * blockDim.x;
    float gbias = gb[0];
    for (int k = i; k < N_NODES; k += stride) {
        g_counts[k] = 0; g_gate[k] = gbias;
    }
    for (int k = i; k < N_GRAPHS; k += stride) g_gcounts[k] = 0;
    for (int k = i; k < NPART; k += stride) { g_lb_flag[k] = 0; g_lb_val[k] = 0; }
    // batch histogram
    for (int v = i; v < N_NODES; v += stride) {
        int b = load_idx(batch, v, is64);
        atomicAdd(&g_gcounts[b], 1);
    }
    // x (50000x64 fp32) -> fp16
    int total2 = N_NODES * 32;
    const float2* x2 = (const float2*)x;
    __half2* xh2 = (__half2*)xh;
    for (int k = i; k < total2; k += stride) {
        float2 v = x2[k];
        xh2[k] = __floats2half2_rn(v.x, v.y);
    }
    // weights -> fp16 transposed [n][k]
    for (int k = i; k < WTOT; k += stride) {
        const float* B; int K, N, idx;
        if (k < WOFF1)      { B = w0; K = 64;  N = 128; idx = k - WOFF0; }
        else if (k < WOFF2) { B = w1; K = 128; N = 256; idx = k - WOFF1; }
        else                { B = w2; K = 256; N = 512; idx = k - WOFF2; }
        int n = idx / K, kk = idx - n * K;
        g_bwh[k] = __float2half_rn(B[(size_t)kk * N + n]);
    }
}

// ---- count degrees; record edge rank within dst bucket + cache decoded dst ----
__global__ void count_kernel(const void* __restrict__ ei) {
    int is64 = g_is64;
    int i = blockIdx.x * blockDim.x + threadIdx.x;
    int stride = gridDim.x * blockDim.x;
    for (int e = i; e < N_EDGES; e += stride) {
        int d = load_idx(ei, (long long)N_EDGES + e, is64);   // dst = edge_index[1]
        g_dstv[e] = d;
        g_rank[e] = atomicAdd(&g_counts[d], 1);
    }
}

// ---- single-pass decoupled-lookback exclusive scan of g_counts -> g_offs
//      (+ fused dinv; block 0 also scans graph offsets) ----
__global__ void __launch_bounds__(256) scan_lookback_kernel() {
    __shared__ int sh[256];
    __shared__ int s_excl;
    int b = blockIdx.x, t = threadIdx.x;
    int i = b * 256 + t;
    int cnt = (i < N_NODES) ? g_counts[i] : 0;
    if (i < N_NODES) g_dinv[i] = rsqrtf((float)(cnt + 1));  // +1 self-loop
    sh[t] = cnt;
    __syncthreads();
    for (int d = 1; d < 256; d <<= 1) {
        int x = (t >= d) ? sh[t - d] : 0;
        __syncthreads();
        sh[t] += x;
        __syncthreads();
    }
    if (t == 0) {
        g_lb_val[b] = sh[255];
        __threadfence();
        g_lb_flag[b] = 1;
    }
    if (t < 32) {
        int sum = 0;
        for (int j = b - 1 - t; j >= 0; j -= 32) {
            while (g_lb_flag[j] == 0) { }
            sum += g_lb_val[j];
        }
#pragma unroll
        for (int o = 16; o > 0; o >>= 1) sum += __shfl_xor_sync(0xffffffffu, sum, o);
        if (t == 0) s_excl = sum;
    }
    __syncthreads();
    int base = s_excl;
    if (i < N_NODES) g_offs[i] = base + sh[t] - cnt;
    if (i == N_NODES - 1) g_offs[N_NODES] = base + sh[t];
    if (b == 0) {
        __syncthreads();
        int gc = g_gcounts[t];
        sh[t] = gc;
        __syncthreads();
        for (int d = 1; d < 256; d <<= 1) {
            int x = (t >= d) ? sh[t - d] : 0;
            __syncthreads();
            sh[t] += x;
            __syncthreads();
        }
        g_goffs[t] = sh[t] - gc;
        if (t == 255) g_goffs[256] = sh[255];
    }
}

// ---- CSR fill: atomic-free; also precompute per-edge weight dinv[s]*dinv[d] ----
__global__ void fill_kernel(const void* __restrict__ ei) {
    int is64 = g_is64;
    int i = blockIdx.x * blockDim.x + threadIdx.x;
    int stride = gridDim.x * blockDim.x;
    for (int e = i; e < N_EDGES; e += stride) {
        int d = g_dstv[e];
        int s = load_idx(ei, e, is64);
        int pos = g_offs[d] + g_rank[e];
        g_csrc[pos] = s;
        g_wedge[pos] = g_dinv[s] * g_dinv[d];   // identical product/order as agg used
    }
}

// ------ GCN aggregation; static warp-per-node; fp16 in/out; sequential edge weights ------
__global__ void __launch_bounds__(256) agg64h_kernel(const __half* __restrict__ h,
                                                     __half* __restrict__ out)
{
    int node = blockIdx.x * 8 + (threadIdx.x >> 5);
    if (node >= N_NODES) return;
    int lane = threadIdx.x & 31;
    float wd = g_dinv[node];
    float2 acc = __half22float2(*(const __half2*)(h + (size_t)node * 64 + lane * 2));
    float ws = wd * wd;
    acc.x *= ws; acc.y *= ws;
    int e = g_offs[node], e1 = g_offs[node + 1];
    for (; e + 4 <= e1; e += 4) {
        int s0 = g_csrc[e], s1 = g_csrc[e + 1], s2 = g_csrc[e + 2], s3 = g_csrc[e + 3];
        float w0 = g_wedge[e],     w1 = g_wedge[e + 1];
        float w2 = g_wedge[e + 2], w3 = g_wedge[e + 3];
        float2 v0 = __half22float2(*(const __half2*)(h + (size_t)s0 * 64 + lane * 2));
        float2 v1 = __half22float2(*(const __half2*)(h + (size_t)s1 * 64 + lane * 2));
        float2 v2 = __half22float2(*(const __half2*)(h + (size_t)s2 * 64 + lane * 2));
        float2 v3 = __half22float2(*(const __half2*)(h + (size_t)s3 * 64 + lane * 2));
        acc.x += v0.x * w0 + v1.x * w1 + v2.x * w2 + v3.x * w3;
        acc.y += v0.y * w0 + v1.y * w1 + v2.y * w2 + v3.y * w3;
    }
    for (; e < e1; e++) {
        int s0 = g_csrc[e];
        float w0 = g_wedge[e];
        float2 v0 = __half22float2(*(const __half2*)(h + (size_t)s0 * 64 + lane * 2));
        acc.x += v0.x * w0; acc.y += v0.y * w0;
    }
    *(__half2*)(out + (size_t)node * 64 + lane * 2) = __floats2half2_rn(acc.x, acc.y);
}

__global__ void __launch_bounds__(256) agg128h_kernel(const __half* __restrict__ h,
                                                      __half* __restrict__ out)
{
    int node = blockIdx.x * 8 + (threadIdx.x >> 5);
    if (node >= N_NODES) return;
    int lane = threadIdx.x & 31;
    float wd = g_dinv[node];
    float acc[4];
    {
        uint2 sv = *(const uint2*)(h + (size_t)node * 128 + lane * 4);
        const __half2* hp = (const __half2*)&sv;
        float ws = wd * wd;
        float2 f0 = __half22float2(hp[0]), f1 = __half22float2(hp[1]);
        acc[0] = f0.x * ws; acc[1] = f0.y * ws; acc[2] = f1.x * ws; acc[3] = f1.y * ws;
    }
    int e = g_offs[node], e1 = g_offs[node + 1];
    for (; e + 4 <= e1; e += 4) {
        int s0 = g_csrc[e], s1 = g_csrc[e + 1], s2 = g_csrc[e + 2], s3 = g_csrc[e + 3];
        float w0 = g_wedge[e],     w1 = g_wedge[e + 1];
        float w2 = g_wedge[e + 2], w3 = g_wedge[e + 3];
        uint2 v0 = *(const uint2*)(h + (size_t)s0 * 128 + lane * 4);
        uint2 v1 = *(const uint2*)(h + (size_t)s1 * 128 + lane * 4);
        uint2 v2 = *(const uint2*)(h + (size_t)s2 * 128 + lane * 4);
        uint2 v3 = *(const uint2*)(h + (size_t)s3 * 128 + lane * 4);
        const __half2* p0 = (const __half2*)&v0;
        const __half2* p1 = (const __half2*)&v1;
        const __half2* p2 = (const __half2*)&v2;
        const __half2* p3 = (const __half2*)&v3;
#pragma unroll
        for (int q = 0; q < 2; q++) {
            float2 f0 = __half22float2(p0[q]);
            float2 f1 = __half22float2(p1[q]);
            float2 f2 = __half22float2(p2[q]);
            float2 f3 = __half22float2(p3[q]);
            acc[2 * q]     += f0.x * w0 + f1.x * w1 + f2.x * w2 + f3.x * w3;
            acc[2 * q + 1] += f0.y * w0 + f1.y * w1 + f2.y * w2 + f3.y * w3;
        }
    }
    for (; e < e1; e++) {
        int s0 = g_csrc[e];
        float w0 = g_wedge[e];
        uint2 v0 = *(const uint2*)(h + (size_t)s0 * 128 + lane * 4);
        const __half2* p0 = (const __half2*)&v0;
#pragma unroll
        for (int q = 0; q < 2; q++) {
            float2 f0 = __half22float2(p0[q]);
            acc[2 * q] += f0.x * w0;
            acc[2 * q + 1] += f0.y * w0;
        }
    }
    __half2 o0 = __floats2half2_rn(acc[0], acc[1]);
    __half2 o1 = __floats2half2_rn(acc[2], acc[3]);
    uint2 ov = make_uint2(*(uint32_t*)&o0, *(uint32_t*)&o1);
    *(uint2*)(out + (size_t)node * 128 + lane * 4) = ov;
}

__global__ void __launch_bounds__(256) agg256h_kernel(const __half* __restrict__ h,
                                                      __half* __restrict__ out)
{
    int node = blockIdx.x * 8 + (threadIdx.x >> 5);
    if (node >= N_NODES) return;
    int lane = threadIdx.x & 31;
    float wd = g_dinv[node];
    float acc[8];
    {
        uint4 sv = *(const uint4*)(h + (size_t)node * 256 + lane * 8);
        const __half2* hp = (const __half2*)&sv;
        float ws = wd * wd;
#pragma unroll
        for (int q = 0; q < 4; q++) {
            float2 f = __half22float2(hp[q]);
            acc[2 * q] = f.x * ws;
            acc[2 * q + 1] = f.y * ws;
        }
    }
    int e = g_offs[node], e1 = g_offs[node + 1];
    for (; e + 4 <= e1; e += 4) {
        int s0 = g_csrc[e], s1 = g_csrc[e + 1], s2 = g_csrc[e + 2], s3 = g_csrc[e + 3];
        float w0 = g_wedge[e],     w1 = g_wedge[e + 1];
        float w2 = g_wedge[e + 2], w3 = g_wedge[e + 3];
        uint4 v0 = *(const uint4*)(h + (size_t)s0 * 256 + lane * 8);
        uint4 v1 = *(const uint4*)(h + (size_t)s1 * 256 + lane * 8);
        uint4 v2 = *(const uint4*)(h + (size_t)s2 * 256 + lane * 8);
        uint4 v3 = *(const uint4*)(h + (size_t)s3 * 256 + lane * 8);
        const __half2* p0 = (const __half2*)&v0;
        const __half2* p1 = (const __half2*)&v1;
        const __half2* p2 = (const __half2*)&v2;
        const __half2* p3 = (const __half2*)&v3;
#pragma unroll
        for (int q = 0; q < 4; q++) {
            float2 f0 = __half22float2(p0[q]);
            float2 f1 = __half22float2(p1[q]);
            float2 f2 = __half22float2(p2[q]);
            float2 f3 = __half22float2(p3[q]);
            acc[2 * q]     += f0.x * w0 + f1.x * w1 + f2.x * w2 + f3.x * w3;
            acc[2 * q + 1] += f0.y * w0 + f1.y * w1 + f2.y * w2 + f3.y * w3;
        }
    }
    for (; e < e1; e++) {
        int n0 = g_csrc[e];
        float w0 = g_wedge[e];
        uint4 v0 = *(const uint4*)(h + (size_t)n0 * 256 + lane * 8);
        const __half2* p0 = (const __half2*)&v0;
#pragma unroll
        for (int q = 0; q < 4; q++) {
            float2 f0 = __half22float2(p0[q]);
            acc[2 * q]     += f0.x * w0;
            acc[2 * q + 1] += f0.y * w0;
        }
    }
    __half2 o0 = __floats2half2_rn(acc[0], acc[1]);
    __half2 o1 = __floats2half2_rn(acc[2], acc[3]);
    __half2 o2 = __floats2half2_rn(acc[4], acc[5]);
    __half2 o3 = __floats2half2_rn(acc[6], acc[7]);
    uint4 ov = make_uint4(*(uint32_t*)&o0, *(uint32_t*)&o1, *(uint32_t*)&o2, *(uint32_t*)&o3);
    *(uint4*)(out + (size_t)node * 256 + lane * 8) = ov;
}

// ---------------- fp16 mma ----------------
__device__ __forceinline__ void mma_f16(float* c, const uint32_t* a, const uint32_t* b) {
    asm volatile(
        "mma.sync.aligned.m16n8k16.row.col.f32.f16.f16.f32 "
        "{%0,%1,%2,%3}, {%4,%5,%6,%7}, {%8,%9}, {%0,%1,%2,%3};"
        : "+f"(c[0]), "+f"(c[1]), "+f"(c[2]), "+f"(c[3])
        : "r"(a[0]), "r"(a[1]), "r"(a[2]), "r"(a[3]), "r"(b[0]), "r"(b[1]));
}

// ---- GEMM + bias + ReLU, fp16 operands, fp32 accum; cp.async double-buffered ----
#define HSTR 40

__global__ void __launch_bounds__(256) gemm_f16_kernel(
    const __half* __restrict__ A, const __half* __restrict__ Bh,
    const float* __restrict__ bias,
    __half* __restrict__ Ch, const float* __restrict__ gatew,
    int M, int N, int K)
{
    __shared__ __align__(16) __half As[2][128 * HSTR];
    __shared__ __align__(16) __half Bhs[2][128 * HSTR];
    __shared__ float sgate[128];

    int tid = threadIdx.x;
    int lane = tid & 31;
    int wid = tid >> 5;
    int warp_m = wid >> 2;
    int warp_n = wid & 3;
    int g = lane >> 2;
    int t = lane & 3;
    int row0 = blockIdx.x * 128;
    int col0 = blockIdx.y * 128;

    if (gatew && tid < 128) sgate[tid] = 0.f;

    float acc[4][4][4];
#pragma unroll
    for (int i = 0; i < 4; i++)
#pragma unroll
        for (int j = 0; j < 4; j++)
#pragma unroll
            for (int r = 0; r < 4; r++) acc[i][j][r] = 0.f;

    int f0 = tid, f1 = tid + 256;
    int ar0 = f0 >> 2, ac0 = (f0 & 3) * 8;
    int ar1 = f1 >> 2, ac1 = (f1 & 3) * 8;

    auto issue_tile = [&](int buf, int k0) {
        {
            int grow = row0 + ar0;
            uint32_t dst = (uint32_t)__cvta_generic_to_shared(&As[buf][ar0 * HSTR + ac0]);
            const __half* src = A + (size_t)grow * K + k0 + ac0;
            int p = (grow < M) ? 16 : 0;
            asm volatile("cp.async.cg.shared.global [%0], [%1], 16, %2;"
                         :: "r"(dst), "l"(src), "r"(p));
        }
        {
            int grow = row0 + ar1;
            uint32_t dst = (uint32_t)__cvta_generic_to_shared(&As[buf][ar1 * HSTR + ac1]);
            const __half* src = A + (size_t)grow * K + k0 + ac1;
            int p = (grow < M) ? 16 : 0;
            asm volatile("cp.async.cg.shared.global [%0], [%1], 16, %2;"
                         :: "r"(dst), "l"(src), "r"(p));
        }
        {
            uint32_t dst = (uint32_t)__cvta_generic_to_shared(&Bhs[buf][ar0 * HSTR + ac0]);
            const __half* src = Bh + (size_t)(col0 + ar0) * K + k0 + ac0;
            asm volatile("cp.async.cg.shared.global [%0], [%1], 16;"
                         :: "r"(dst), "l"(src));
        }
        {
            uint32_t dst = (uint32_t)__cvta_generic_to_shared(&Bhs[buf][ar1 * HSTR + ac1]);
            const __half* src = Bh + (size_t)(col0 + ar1) * K + k0 + ac1;
            asm volatile("cp.async.cg.shared.global [%0], [%1], 16;"
                         :: "r"(dst), "l"(src));
        }
        asm volatile("cp.async.commit_group;");
    };

    int nIter = K >> 5;
    issue_tile(0, 0);
    int buf = 0;
    for (int it = 0; it < nIter; it++) {
        if (it + 1 < nIter) {
            issue_tile(buf ^ 1, (it + 1) * 32);
            asm volatile("cp.async.wait_group 1;");
        } else {
            asm volatile("cp.async.wait_group 0;");
        }
        __syncthreads();

        const __half* Ab = As[buf];
        const __half* Bb = Bhs[buf];
#pragma unroll
        for (int kc = 0; kc < 2; kc++) {
            uint32_t bh[4][2];
#pragma unroll
            for (int tn = 0; tn < 4; tn++) {
                int n = warp_n * 32 + tn * 8 + g;
                int base = n * HSTR + kc * 16 + 2 * t;
                bh[tn][0] = *(const uint32_t*)&Bb[base];
                bh[tn][1] = *(const uint32_t*)&Bb[base + 8];
            }
#pragma unroll
            for (int tm = 0; tm < 4; tm++) {
                int row = warp_m * 64 + tm * 16 + g;
                int base = row * HSTR + kc * 16 + 2 * t;
                uint32_t a[4];
                a[0] = *(const uint32_t*)&Ab[base];
                a[1] = *(const uint32_t*)&Ab[base + 8 * HSTR];
                a[2] = *(const uint32_t*)&Ab[base + 8];
                a[3] = *(const uint32_t*)&Ab[base + 8 * HSTR + 8];
#pragma unroll
                for (int tn = 0; tn < 4; tn++) {
                    mma_f16(acc[tm][tn], a, bh[tn]);
                }
            }
        }
        __syncthreads();
        buf ^= 1;
    }

    float bv[4][2], gwv[4][2];
#pragma unroll
    for (int tn = 0; tn < 4; tn++) {
        int col = col0 + warp_n * 32 + tn * 8 + 2 * t;
        bv[tn][0] = bias[col];
        bv[tn][1] = bias[col + 1];
        if (gatew) { gwv[tn][0] = gatew[col]; gwv[tn][1] = gatew[col + 1]; }
    }
#pragma unroll
    for (int tm = 0; tm < 4; tm++) {
        int row = row0 + warp_m * 64 + tm * 16 + g;
        float p0 = 0.f, p1 = 0.f;
#pragma unroll
        for (int tn = 0; tn < 4; tn++) {
            int col = col0 + warp_n * 32 + tn * 8 + 2 * t;
            float v0 = fmaxf(acc[tm][tn][0] + bv[tn][0], 0.f);
            float v1 = fmaxf(acc[tm][tn][1] + bv[tn][1], 0.f);
            float v2 = fmaxf(acc[tm][tn][2] + bv[tn][0], 0.f);
            float v3 = fmaxf(acc[tm][tn][3] + bv[tn][1], 0.f);
            if (row < M)     *(__half2*)(Ch + (size_t)row * N + col)       = __floats2half2_rn(v0, v1);
            if (row + 8 < M) *(__half2*)(Ch + (size_t)(row + 8) * N + col) = __floats2half2_rn(v2, v3);
            if (gatew) {
                p0 += v0 * gwv[tn][0] + v1 * gwv[tn][1];
                p1 += v2 * gwv[tn][0] + v3 * gwv[tn][1];
            }
        }
        if (gatew) {
            p0 += __shfl_xor_sync(0xffffffffu, p0, 1);
            p0 += __shfl_xor_sync(0xffffffffu, p0, 2);
            p1 += __shfl_xor_sync(0xffffffffu, p1, 1);
            p1 += __shfl_xor_sync(0xffffffffu, p1, 2);
            if (t == 0) {
                int rl = warp_m * 64 + tm * 16 + g;
                atomicAdd(&sgate[rl], p0);
                atomicAdd(&sgate[rl + 8], p1);
            }
        }
    }
    if (gatew) {
        __syncthreads();
        if (tid < 128 && row0 + tid < M) atomicAdd(&g_gate[row0 + tid], sgate[tid]);
    }
}

// ------- segment softmax + weighted sum over fp16 x -> graph embeddings [G, 512] -------
__global__ void __launch_bounds__(256) softmax_emb_kernel(const __half* __restrict__ xh)
{
    __shared__ float red[8];
    __shared__ float salpha[256];
    __shared__ float bcast;
    int g = blockIdx.x, tid = threadIdx.x;
    int lane = tid & 31, wid = tid >> 5;
    int s = g_goffs[g], e = g_goffs[g + 1];

    float m = -INFINITY;
    for (int i = s + tid; i < e; i += 256) m = fmaxf(m, g_gate[i]);
#pragma unroll
    for (int o = 16; o > 0; o >>= 1) m = fmaxf(m, __shfl_xor_sync(0xffffffffu, m, o));
    if (lane == 0) red[wid] = m;
    __syncthreads();
    if (wid == 0) {
        float x = (lane < 8) ? red[lane] : -INFINITY;
#pragma unroll
        for (int o = 4; o > 0; o >>= 1) x = fmaxf(x, __shfl_xor_sync(0xffffffffu, x, o));
        if (lane == 0) bcast = x;
    }
    __syncthreads();
    m = bcast;

    float sum = 0.f;
    for (int i = s + tid; i < e; i += 256) sum += expf(g_gate[i] - m);
#pragma unroll
    for (int o = 16; o > 0; o >>= 1) sum += __shfl_xor_sync(0xffffffffu, sum, o);
    if (lane == 0) red[wid] = sum;
    __syncthreads();
    if (wid == 0) {
        float x = (lane < 8) ? red[lane] : 0.f;
#pragma unroll
        for (int o = 4; o > 0; o >>= 1) x += __shfl_xor_sync(0xffffffffu, x, o);
        if (lane == 0) bcast = x;
    }
    __syncthreads();
    float inv = (e > s) ? 1.f / bcast : 0.f;

    // thread owns columns 2*tid, 2*tid+1; inner row loop unrolled x4 (order-preserving)
    float2 acc = make_float2(0.f, 0.f);
    for (int start = s; start < e; start += 256) {
        int i = start + tid;
        salpha[tid] = (i < e) ? expf(g_gate[i] - m) * inv : 0.f;
        __syncthreads();
        int cnt = min(256, e - start);
        const __half2* base = (const __half2*)(xh + (size_t)start * 512);
        int k = 0;
        for (; k + 4 <= cnt; k += 4) {
            float a0 = salpha[k],     a1 = salpha[k + 1];
            float a2 = salpha[k + 2], a3 = salpha[k + 3];
            float2 f0 = __half22float2(base[(size_t)(k)     * 256 + tid]);
            float2 f1 = __half22float2(base[(size_t)(k + 1) * 256 + tid]);
            float2 f2 = __half22float2(base[(size_t)(k + 2) * 256 + tid]);
            float2 f3 = __half22float2(base[(size_t)(k + 3) * 256 + tid]);
            acc.x += f0.x * a0; acc.y += f0.y * a0;
            acc.x += f1.x * a1; acc.y += f1.y * a1;
            acc.x += f2.x * a2; acc.y += f2.y * a2;
            acc.x += f3.x * a3; acc.y += f3.y * a3;
        }
        for (; k < cnt; k++) {
            float a = salpha[k];
            float2 f = __half22float2(base[(size_t)k * 256 + tid]);
            acc.x += f.x * a;
            acc.y += f.y * a;
        }
        __syncthreads();
    }
    g_emb[g * 512 + 2 * tid]     = acc.x;
    g_emb[g * 512 + 2 * tid + 1] = acc.y;
}

// ---- fused GRU layer: h[g,c] = (1-z)*n; gi = A@wih^T (+bih), gh bias = bhh; h0=0 ----
#define GF_BK 32

__global__ void __launch_bounds__(256) gru_fused_kernel(
    const float* __restrict__ A, const float* __restrict__ W,
    const float* __restrict__ bih, const float* __restrict__ bhh,
    float* __restrict__ hout, int K)
{
    __shared__ float As[GF_BK][33];
    __shared__ float Ws[3][16][GF_BK + 1];
    int tid = threadIdx.x;
    int row0 = blockIdx.x * 32;
    int c0 = blockIdx.y * 16;
    int tn = tid & 15, tm = tid >> 4;
    float acc[3][2] = {};

    for (int k0 = 0; k0 < K; k0 += GF_BK) {
#pragma unroll
        for (int l = 0; l < 4; l++) {
            int f = tid + l * 256;
            int r = f >> 5, c = f & 31;
            As[c][r] = A[(size_t)(row0 + r) * K + k0 + c];
        }
#pragma unroll
        for (int l = 0; l < 6; l++) {
            int f = tid + l * 256;
            int gate = f >> 9;
            int rem = f & 511;
            int n = rem >> 5, c = rem & 31;
            Ws[gate][n][c] = W[(size_t)(gate * 256 + c0 + n) * K + k0 + c];
        }
        __syncthreads();
#pragma unroll
        for (int k = 0; k < GF_BK; k++) {
            float a0 = As[k][tm * 2];
            float a1 = As[k][tm * 2 + 1];
            float wr = Ws[0][tn][k], wz = Ws[1][tn][k], wn = Ws[2][tn][k];
            acc[0][0] += a0 * wr; acc[0][1] += a1 * wr;
            acc[1][0] += a0 * wz; acc[1][1] += a1 * wz;
            acc[2][0] += a0 * wn; acc[2][1] += a1 * wn;
        }
        __syncthreads();
    }

    int c = c0 + tn;
    float br = bih[c] + bhh[c];
    float bz = bih[c + 256] + bhh[c + 256];
    float bn_i = bih[c + 512];
    float bn_h = bhh[c + 512];
#pragma unroll
    for (int i = 0; i < 2; i++) {
        int g = row0 + tm * 2 + i;
        float r = 1.f / (1.f + expf(-(acc[0][i] + br)));
        float z = 1.f / (1.f + expf(-(acc[1][i] + bz)));
        float n = tanhf(acc[2][i] + bn_i + r * bn_h);
        hout[g * GRUH + c] = (1.f - z) * n;
    }
}

// ---- projection GEMM: out[G,N] = A[G,K] @ W[N,K]^T + bias; tiles 32x64, BK=32 ----
__global__ void __launch_bounds__(256) proj_gemm_kernel(
    const float* __restrict__ A, const float* __restrict__ W,
    const float* __restrict__ bias, float* __restrict__ C,
    int N, int K)
{
    __shared__ float As[32][33];
    __shared__ float Ws[64][33];
    int tid = threadIdx.x;
    int row0 = blockIdx.x * 32;
    int col0 = blockIdx.y * 64;
    int tn = tid & 15, tm = tid >> 4;
    float acc[2][4] = {};

    for (int k0 = 0; k0 < K; k0 += 32) {
#pragma unroll
        for (int l = 0; l < 4; l++) {
            int f = tid + l * 256;
            int r = f >> 5, c = f & 31;
            As[c][r] = A[(size_t)(row0 + r) * K + k0 + c];
        }
#pragma unroll
        for (int l = 0; l < 8; l++) {
            int f = tid + l * 256;
            int n = f >> 5, c = f & 31;
            Ws[n][c] = W[(size_t)(col0 + n) * K + k0 + c];
        }
        __syncthreads();
#pragma unroll
        for (int k = 0; k < 32; k++) {
            float a0 = As[k][tm * 2];
            float a1 = As[k][tm * 2 + 1];
#pragma unroll
            for (int j = 0; j < 4; j++) {
                float b = Ws[tn * 4 + j][k];
                acc[0][j] += a0 * b;
                acc[1][j] += a1 * b;
            }
        }
        __syncthreads();
    }
#pragma unroll
    for (int i = 0; i < 2; i++) {
        int gg = row0 + tm * 2 + i;
#pragma unroll
        for (int j = 0; j < 4; j++) {
            int nn = col0 + tn * 4 + j;
            C[(size_t)gg * N + nn] = acc[i][j] + bias[nn];
        }
    }
}

// ---------------- launch ----------------
extern "C" void kernel_launch(void* const* d_in, const int* in_sizes, int n_in,
                              void* d_out, int out_size)
{
    const float* x       = (const float*)d_in[0];
    const void*  ei      = d_in[1];
    const void*  batch   = d_in[2];
    const float* w0 = (const float*)d_in[3];  const float* b0 = (const float*)d_in[4];
    const float* w1 = (const float*)d_in[5];  const float* b1 = (const float*)d_in[6];
    const float* w2 = (const float*)d_in[7];  const float* b2 = (const float*)d_in[8];
    const float* gate_w = (const float*)d_in[9];
    const float* gate_b = (const float*)d_in[10];
    const float* wih0 = (const float*)d_in[11];
    const float* bih0 = (const float*)d_in[13];
    const float* bhh0 = (const float*)d_in[14];
    const float* wih1 = (const float*)d_in[15];
    const float* bih1 = (const float*)d_in[17];
    const float* bhh1 = (const float*)d_in[18];
    const float* proj_w = (const float*)d_in[19];
    const float* proj_b = (const float*)d_in[20];
    float* out = (float*)d_out;

    __half *pH, *pA, *pWh;
    float *pEmb, *pH1, *pH2;
    cudaGetSymbolAddress((void**)&pH,   g_hbuf);
    cudaGetSymbolAddress((void**)&pA,   g_abuf);
    cudaGetSymbolAddress((void**)&pWh,  g_bwh);
    cudaGetSymbolAddress((void**)&pEmb, g_emb);
    cudaGetSymbolAddress((void**)&pH1,  g_h1);
    cudaGetSymbolAddress((void**)&pH2,  g_h2);

    // preprocessing
    init_kernel<<<256, 256>>>((const int*)ei, gate_b, x, pH, batch, w0, w1, w2);
    count_kernel<<<1024, 256>>>(ei);
    scan_lookback_kernel<<<NPART, 256>>>();
    fill_kernel<<<1024, 256>>>(ei);

    int gM = (N_NODES + 127) / 128;
    int gAgg = (N_NODES + 7) / 8;

    // GCN layers (fp16 agg -> fp16 GEMM, cp.async pipelined)
    agg64h_kernel<<<gAgg, 256>>>(pH, pA);
    gemm_f16_kernel<<<dim3(gM, 1), 256>>>(pA, pWh + WOFF0, b0, pH, nullptr,
                                          N_NODES, 128, 64);
    agg128h_kernel<<<gAgg, 256>>>(pH, pA);
    gemm_f16_kernel<<<dim3(gM, 2), 256>>>(pA, pWh + WOFF1, b1, pH, nullptr,
                                          N_NODES, 256, 128);
    agg256h_kernel<<<gAgg, 256>>>(pH, pA);
    gemm_f16_kernel<<<dim3(gM, 4), 256>>>(pA, pWh + WOFF2, b2, pH, gate_w,
                                          N_NODES, 512, 256);

    // attentional aggregation
    softmax_emb_kernel<<<N_GRAPHS, 256>>>(pH);

    // fused GRU layers + projection
    gru_fused_kernel<<<dim3(N_GRAPHS / 32, GRUH / 16), 256>>>(pEmb, wih0, bih0, bhh0, pH1, 512);
    gru_fused_kernel<<<dim3(N_GRAPHS / 32, GRUH / 16), 256>>>(pH1, wih1, bih1, bhh1, pH2, 256);
    proj_gemm_kernel<<<dim3(N_GRAPHS / 32, 512 / 64), 256>>>(pH2, proj_w, proj_b, out, 512, 256);
}